// round 14
// baseline (speedup 1.0000x reference)
#include <cuda_runtime.h>
#include <cuda_fp16.h>
#include <stdint.h>
#include <math.h>

// Problem constants
#define Bb   2
#define Ss   2048
#define Dd   1024
#define Hh   16
#define HDd  64
#define Mrows (Bb*Ss)   // 4096

#define SC2 0.18033688011112042f   // 0.125 * log2(e), folded into Q
#define LOG2E 1.4426950408889634f

// ---------------- scratch (no allocs allowed) ----------------
__device__ uint16_t g_xh [Mrows * Dd];            // x fp16 (plain)
__device__ uint16_t g_wh [3072 * Dd];             // fused wq|wk|wv fp16
__device__ uint16_t g_woh[Dd * Dd];               // wo fp16
__device__ uint16_t g_qh [Mrows * Dd];            // [B,H,S,64] fp16 (pre-scaled)
__device__ uint16_t g_kh [Mrows * Dd];            // fp16
__device__ uint16_t g_vh [Mrows * Dd];            // fp16 (plain)
__device__ uint16_t g_aoh[Mrows * Dd];            // attn out fp16 (plain)
__device__ float    g_cosT[Ss * 32];              // rope tables
__device__ float    g_sinT[Ss * 32];

// ================= PTX helpers ==========================
__device__ __forceinline__ uint32_t smem_u32(const void* p) {
    uint32_t a;
    asm("{ .reg .u64 t; cvta.to.shared.u64 t, %1; cvt.u32.u64 %0, t; }"
        : "=r"(a) : "l"(p));
    return a;
}
__device__ __forceinline__ void cp_async16(uint32_t s, const void* g) {
    asm volatile("cp.async.cg.shared.global [%0], [%1], 16;" :: "r"(s), "l"(g));
}
#define CP_COMMIT() asm volatile("cp.async.commit_group;" ::: "memory")
#define CP_WAIT(n)  asm volatile("cp.async.wait_group %0;" :: "n"(n) : "memory")

#define LDSM_X4(r, addr) \
    asm volatile("ldmatrix.sync.aligned.m8n8.x4.shared.b16 {%0,%1,%2,%3}, [%4];" \
        : "=r"((r)[0]), "=r"((r)[1]), "=r"((r)[2]), "=r"((r)[3]) : "r"(addr))
#define LDSM_X4_T(r, addr) \
    asm volatile("ldmatrix.sync.aligned.m8n8.x4.trans.shared.b16 {%0,%1,%2,%3}, [%4];" \
        : "=r"((r)[0]), "=r"((r)[1]), "=r"((r)[2]), "=r"((r)[3]) : "r"(addr))

#define MMA_F16(d, a, b0, b1) \
    asm volatile("mma.sync.aligned.m16n8k16.row.col.f32.f16.f16.f32 " \
        "{%0,%1,%2,%3}, {%4,%5,%6,%7}, {%8,%9}, {%0,%1,%2,%3};" \
        : "+f"((d)[0]), "+f"((d)[1]), "+f"((d)[2]), "+f"((d)[3]) \
        : "r"((a)[0]), "r"((a)[1]), "r"((a)[2]), "r"((a)[3]), \
          "r"(b0), "r"(b1))

__device__ __forceinline__ uint32_t pack_h2(float a, float b) {
    uint32_t r;
    asm("cvt.rn.f16x2.f32 %0, %1, %2;" : "=r"(r) : "f"(b), "f"(a));
    return r;
}
__device__ __forceinline__ float ex2f(float x) {
    float y;
    asm("ex2.approx.f32 %0, %1;" : "=f"(y) : "f"(x));
    return y;
}

// =================================================================
// fused convert: x, w, wo -> plain fp16 ; rope tables in own blocks
// =================================================================
__global__ __launch_bounds__(256)
void cvt_all(const float4* __restrict__ x,  const float4* __restrict__ wq,
             const float4* __restrict__ wk, const float4* __restrict__ wv,
             const float4* __restrict__ wo,
             uint2* __restrict__ xh, uint2* __restrict__ wh,
             uint2* __restrict__ woh,
             float* __restrict__ cosT, float* __restrict__ sinT) {
    int i = blockIdx.x * 256 + threadIdx.x;
    if (i >= 2097152) {   // rope-table blocks
        int t = i - 2097152;
        if (t < 65536) {
            int s = t >> 5, j = t & 31;
            float inv = exp2f(-(float)j * 0.4152410118609203f); // log2(1e4)/32
            float sn, cs;
            sincosf((float)s * inv, &sn, &cs);
            cosT[t] = cs;
            sinT[t] = sn;
        }
        return;
    }
    const float4* src;
    uint2* dst;
    if (i < 1048576) {
        src = x + i; dst = xh + i;
    } else {
        int i2 = i - 1048576;
        int reg = i2 >> 18;            // 0..3
        int off = i2 & 262143;
        if (reg == 0)      { src = wq + off; dst = wh + off; }
        else if (reg == 1) { src = wk + off; dst = wh + 262144 + off; }
        else if (reg == 2) { src = wv + off; dst = wh + 524288 + off; }
        else               { src = wo + off; dst = woh + off; }
    }
    float4 v = *src;
    uint2 o;
    o.x = pack_h2(v.x, v.y);
    o.y = pack_h2(v.z, v.w);
    *dst = o;
}

// =================================================================
// GEMM framework: plain fp16 HMMA, tile 256x128x64, 256 thr (8 warps),
// warps 4(M)x2(N), warp tile 64x64, 3-stage cp.async ring, 1 CTA/SM.
// Crossbar traffic per MAC halved vs 128x128 warp-32x64.
// =================================================================
#define GK 1024
#define GPITCH 144                // 64 f16 = 128B + 16B pad
#define P_A  0                    // 256*144 = 36864
#define P_B  36864                // 128*144 = 18432
#define P_STG 55296
#define GEMM1_SMEM (3 * P_STG)    // 165888

#define GEMM_PREAMBLE                                                        \
    extern __shared__ char smem[];                                           \
    const uint32_t sb = smem_u32(smem);                                      \
    const int tid = threadIdx.x;                                             \
    const int wid = tid >> 5, lane = tid & 31;                               \
    const int wm = wid & 3, wn = wid >> 2;                                   \
    const int gid = lane >> 2, tig = lane & 3;                               \
    const int bm = blockIdx.y * 256, bn = blockIdx.x * 128;                  \
    uint32_t aAddr[4], bAddr[4];                                             \
    _Pragma("unroll")                                                        \
    for (int mf = 0; mf < 4; ++mf)                                           \
        aAddr[mf] = (wm * 64 + mf * 16 + (lane & 15)) * GPITCH               \
                    + (lane >> 4) * 16;                                      \
    _Pragma("unroll")                                                        \
    for (int nb = 0; nb < 4; ++nb)                                           \
        bAddr[nb] = (wn * 64 + nb * 16 + ((lane >> 4) << 3)                  \
                    + (lane & 7)) * GPITCH + ((lane >> 3) & 1) * 16;         \
    float acc[4][8][4];                                                      \
    _Pragma("unroll")                                                        \
    for (int i = 0; i < 4; ++i)                                              \
        _Pragma("unroll")                                                    \
        for (int j = 0; j < 8; ++j)                                          \
            _Pragma("unroll")                                                \
            for (int c = 0; c < 4; ++c) acc[i][j][c] = 0.f;

__device__ __forceinline__ void gemm1_issue(
    uint32_t stg, const uint16_t* __restrict__ A,
    const uint16_t* __restrict__ B, int bm, int bn, int k0, int tid) {
#pragma unroll
    for (int u = 0; u < 8; ++u) {       // A: 256 rows x 8 chunks
        int q = tid + u * 256;          // 0..2047
        int r = q >> 3, c = q & 7;
        cp_async16(stg + P_A + r * GPITCH + c * 16,
                   A + (size_t)(bm + r) * GK + k0 + c * 8);
    }
#pragma unroll
    for (int u = 0; u < 4; ++u) {       // B: 128 rows x 8 chunks
        int q = tid + u * 256;          // 0..1023
        int r = q >> 3, c = q & 7;
        cp_async16(stg + P_B + r * GPITCH + c * 16,
                   B + (size_t)(bn + r) * GK + k0 + c * 8);
    }
}

#define GEMM1_MAINLOOP(A, B, bm, bn)                                         \
    gemm1_issue(sb, A, B, bm, bn, 0, tid);                                   \
    CP_COMMIT();                                                             \
    gemm1_issue(sb + P_STG, A, B, bm, bn, 64, tid);                          \
    CP_COMMIT();                                                             \
    for (int s = 0; s < 16; ++s) {                                           \
        if (s < 15) { CP_WAIT(1); } else { CP_WAIT(0); }                     \
        __syncthreads();                                                     \
        if (s + 2 < 16) {                                                    \
            gemm1_issue(sb + ((s + 2) % 3) * P_STG, A, B,                    \
                        bm, bn, (s + 2) * 64, tid);                          \
            CP_COMMIT();                                                     \
        }                                                                    \
        const uint32_t stg = sb + (s % 3) * P_STG;                           \
        _Pragma("unroll")                                                    \
        for (int ks = 0; ks < 4; ++ks) {                                     \
            uint32_t bh4[4][4];                                              \
            _Pragma("unroll")                                                \
            for (int nb = 0; nb < 4; ++nb)                                   \
                LDSM_X4(bh4[nb], stg + P_B + bAddr[nb] + ks * 32);           \
            _Pragma("unroll")                                                \
            for (int mf = 0; mf < 4; ++mf) {                                 \
                uint32_t ah[4];                                              \
                LDSM_X4(ah, stg + P_A + aAddr[mf] + ks * 32);                \
                _Pragma("unroll")                                            \
                for (int nb = 0; nb < 4; ++nb) {                             \
                    MMA_F16(acc[mf][2*nb],   ah, bh4[nb][0], bh4[nb][1]);    \
                    MMA_F16(acc[mf][2*nb+1], ah, bh4[nb][2], bh4[nb][3]);    \
                }                                                            \
            }                                                                \
        }                                                                    \
    }

// =================================================================
// QKV GEMM with fused RMSNorm+RoPE epilogue (Q pre-scaled by SC2).
// =================================================================
__global__ __launch_bounds__(256, 1)
void gemm_qkv(const uint16_t* __restrict__ A, const uint16_t* __restrict__ B,
              const float* __restrict__ qw, const float* __restrict__ kw,
              const float* __restrict__ cosT, const float* __restrict__ sinT,
              uint16_t* __restrict__ qh, uint16_t* __restrict__ kh,
              uint16_t* __restrict__ vh) {
    GEMM_PREAMBLE
    GEMM1_MAINLOOP(A, B, bm, bn)

    const int cb = bn + wn * 64;
    const int sect = cb >> 10;          // 0=Q, 1=K, 2=V
    const int hh = (cb >> 6) & 15;

#pragma unroll
    for (int mf = 0; mf < 4; ++mf) {
#pragma unroll
        for (int hf = 0; hf < 2; ++hf) {
            const int row = bm + wm * 64 + mf * 16 + gid + hf * 8;
            const int s = row & (Ss - 1);
            const int b = row >> 11;
            const size_t dst = (((size_t)(b * Hh + hh)) * Ss + s) * HDd;
            float v[8][2];
#pragma unroll
            for (int nf = 0; nf < 8; ++nf) {
                v[nf][0] = acc[mf][nf][hf * 2];
                v[nf][1] = acc[mf][nf][hf * 2 + 1];
            }
            if (sect == 2) {   // V: plain fp16
#pragma unroll
                for (int nf = 0; nf < 8; ++nf) {
                    int d0 = nf * 8 + tig * 2;
                    *(uint32_t*)&vh[dst + d0] = pack_h2(v[nf][0], v[nf][1]);
                }
            } else {           // Q or K: rms + rope, plain fp16
                float ss = 0.f;
#pragma unroll
                for (int nf = 0; nf < 8; ++nf)
                    ss += v[nf][0] * v[nf][0] + v[nf][1] * v[nf][1];
                ss += __shfl_xor_sync(0xffffffffu, ss, 1);
                ss += __shfl_xor_sync(0xffffffffu, ss, 2);
                float r = rsqrtf(ss * (1.0f / 64.0f) + 1e-6f);
                const float* w = sect ? kw : qw;
                uint16_t* outp = sect ? kh : qh;
                if (sect == 0) r *= SC2;   // fold softmax scale into Q
#pragma unroll
                for (int nf = 0; nf < 4; ++nf) {
                    int d0 = nf * 8 + tig * 2;
                    float2 w1 = *(const float2*)&w[d0];
                    float2 w2 = *(const float2*)&w[d0 + 32];
                    float2 cs = *(const float2*)&cosT[s * 32 + d0];
                    float2 sn = *(const float2*)&sinT[s * 32 + d0];
                    float x1a = v[nf][0]     * r * w1.x;
                    float x1b = v[nf][1]     * r * w1.y;
                    float x2a = v[nf + 4][0] * r * w2.x;
                    float x2b = v[nf + 4][1] * r * w2.y;
                    float o1a = x1a * cs.x - x2a * sn.x;
                    float o1b = x1b * cs.y - x2b * sn.y;
                    float o2a = x2a * cs.x + x1a * sn.x;
                    float o2b = x2b * cs.y + x1b * sn.y;
                    *(uint32_t*)&outp[dst + d0]      = pack_h2(o1a, o1b);
                    *(uint32_t*)&outp[dst + d0 + 32] = pack_h2(o2a, o2b);
                }
            }
        }
    }
}

// =================================================================
// Output-projection GEMM (plain fp16 A, fp32 C)
// =================================================================
__global__ __launch_bounds__(256, 1)
void gemm_out(const uint16_t* __restrict__ A, const uint16_t* __restrict__ B,
              float* __restrict__ C) {
    GEMM_PREAMBLE
    GEMM1_MAINLOOP(A, B, bm, bn)
#pragma unroll
    for (int mf = 0; mf < 4; ++mf) {
        const int row = bm + wm * 64 + mf * 16 + gid;
#pragma unroll
        for (int nf = 0; nf < 8; ++nf) {
            const int col = bn + wn * 64 + nf * 8 + tig * 2;
            *(float2*)&C[(size_t)row * Dd + col] =
                make_float2(acc[mf][nf][0], acc[mf][nf][1]);
            *(float2*)&C[(size_t)(row + 8) * Dd + col] =
                make_float2(acc[mf][nf][2], acc[mf][nf][3]);
        }
    }
}

// =================================================================
// fp16 flash attention: Q plain (pre-scaled), K plain, V plain.
// Br=128, Bc=64, 256 threads, 4-stage KV ring, 2 CTAs/SM. (R13)
// =================================================================
#define APITCH 144
#define A_Q  0
#define A_QSZ 18432               // 128*144
#define A_K  0
#define A_V  9216
#define A_STG 18432
#define ATTN_SMEM (A_QSZ + 4 * A_STG)   // 92160
#define ONES_H2 0x3C003C00u

__device__ __forceinline__ void attn_kv_issue(
    uint32_t stg, const uint16_t* __restrict__ kh,
    const uint16_t* __restrict__ vh, size_t seqbase, int j, int tid) {
#pragma unroll
    for (int u = 0; u < 2; ++u) {
        int q = tid + u * 256;          // 0..511
        int r = q >> 3, c = q & 7;
        size_t src = seqbase + (size_t)(j * 64 + r) * 64 + c * 8;
        uint32_t d = r * APITCH + c * 16;
        cp_async16(stg + A_K + d, kh + src);
        cp_async16(stg + A_V + d, vh + src);
    }
}

__global__ __launch_bounds__(256, 2)
void attn_tc(const uint16_t* __restrict__ qh,
             const uint16_t* __restrict__ kh, const uint16_t* __restrict__ vh,
             const float* __restrict__ sinkl,
             uint16_t* __restrict__ aoh) {
    extern __shared__ char smem[];
    const uint32_t sb = smem_u32(smem);
    const int tid = threadIdx.x;
    const int wid = tid >> 5, lane = tid & 31;
    const int gid = lane >> 2, tig = lane & 3;
    const int qb = gridDim.x - 1 - blockIdx.x;   // heavy tiles first
    const int bh = blockIdx.y;
    const int h  = bh & (Hh - 1);
    const int b  = bh >> 4;
    const size_t seqbase = (size_t)bh * Ss * HDd;
    const int q0 = qb * 128;
    const int jmax = 2 * qb + 1;

    // ---- prologue: Q tile (plain) + KV stages 0,1,2 ----
#pragma unroll
    for (int u = 0; u < 2; ++u) {
        int q = tid + u * 256;              // 0..511
        int r = q >> 2, c = q & 3;          // 128 rows x 4 chunks
        size_t src = seqbase + (size_t)(q0 + r) * 64 + c * 16;
        uint32_t d = r * APITCH + c * 32;
        cp_async16(sb + A_Q + d, qh + src);
        cp_async16(sb + A_Q + d + 16, qh + src + 8);
    }
    attn_kv_issue(sb + A_QSZ, kh, vh, seqbase, 0, tid);
    CP_COMMIT();
    if (1 <= jmax) {
        attn_kv_issue(sb + A_QSZ + A_STG, kh, vh, seqbase, 1, tid);
    }
    CP_COMMIT();
    if (2 <= jmax) {
        attn_kv_issue(sb + A_QSZ + 2 * A_STG, kh, vh, seqbase, 2, tid);
    }
    CP_COMMIT();

    const uint32_t qA = sb + A_Q + (wid * 16 + (lane & 15)) * APITCH
                        + (lane >> 4) * 16;
    uint32_t kB[4];
#pragma unroll
    for (int nb = 0; nb < 4; ++nb)
        kB[nb] = A_K + (nb * 16 + ((lane >> 4) << 3) + (lane & 7)) * APITCH
                 + ((lane >> 3) & 1) * 16;
    const uint32_t vBrel = A_V + (lane & 15) * APITCH + (lane >> 4) * 16;

    const float snk2 = sinkl[h] * LOG2E;
    float m0 = snk2, m1 = snk2;
    float o[8][4], ol[4];
#pragma unroll
    for (int i = 0; i < 8; ++i)
#pragma unroll
        for (int c = 0; c < 4; ++c) o[i][c] = 0.f;
#pragma unroll
    for (int c = 0; c < 4; ++c) ol[c] = 0.f;

    const int r0g = q0 + wid * 16 + gid;
    const int r1g = r0g + 8;

    for (int j = 0; j <= jmax; ++j) {
        if (j + 2 <= jmax)      { CP_WAIT(2); }
        else if (j + 1 <= jmax) { CP_WAIT(1); }
        else                    { CP_WAIT(0); }
        __syncthreads();
        if (j + 3 <= jmax) {
            attn_kv_issue(sb + A_QSZ + ((j + 3) & 3) * A_STG,
                          kh, vh, seqbase, j + 3, tid);
            CP_COMMIT();
        }
        const uint32_t stg = sb + A_QSZ + (j & 3) * A_STG;

        // ---- S = Q K^T (both plain fp16, Q pre-scaled) ----
        float s[8][4];
#pragma unroll
        for (int i = 0; i < 8; ++i)
#pragma unroll
            for (int c = 0; c < 4; ++c) s[i][c] = 0.f;

#pragma unroll
        for (int ks = 0; ks < 4; ++ks) {
            uint32_t qa[4];
            LDSM_X4(qa, qA + ks * 32);
#pragma unroll
            for (int nb = 0; nb < 4; ++nb) {
                uint32_t kb4[4];
                LDSM_X4(kb4, stg + kB[nb] + ks * 32);
                MMA_F16(s[2*nb],   qa, kb4[0], kb4[1]);
                MMA_F16(s[2*nb+1], qa, kb4[2], kb4[3]);
            }
        }

        // ---- causal mask (diagonal blocks only) ----
        if (j >= 2 * qb) {
#pragma unroll
            for (int nf = 0; nf < 8; ++nf)
#pragma unroll
                for (int c = 0; c < 4; ++c) {
                    int col = j * 64 + nf * 8 + tig * 2 + (c & 1);
                    int row = (c < 2) ? r0g : r1g;
                    if (col > row) s[nf][c] = -1e30f;
                }
        }

        // ---- online softmax (base-2) ----
        float mx0 = -1e30f, mx1 = -1e30f;
#pragma unroll
        for (int nf = 0; nf < 8; ++nf) {
            mx0 = fmaxf(mx0, fmaxf(s[nf][0], s[nf][1]));
            mx1 = fmaxf(mx1, fmaxf(s[nf][2], s[nf][3]));
        }
        mx0 = fmaxf(mx0, __shfl_xor_sync(0xffffffffu, mx0, 1));
        mx0 = fmaxf(mx0, __shfl_xor_sync(0xffffffffu, mx0, 2));
        mx1 = fmaxf(mx1, __shfl_xor_sync(0xffffffffu, mx1, 1));
        mx1 = fmaxf(mx1, __shfl_xor_sync(0xffffffffu, mx1, 2));
        const float mn0 = fmaxf(m0, mx0), mn1 = fmaxf(m1, mx1);
        const float cr0 = ex2f(m0 - mn0), cr1 = ex2f(m1 - mn1);
        m0 = mn0; m1 = mn1;
#pragma unroll
        for (int nf = 0; nf < 8; ++nf) {
            o[nf][0] *= cr0; o[nf][1] *= cr0;
            o[nf][2] *= cr1; o[nf][3] *= cr1;
        }
        ol[0] *= cr0; ol[1] *= cr0; ol[2] *= cr1; ol[3] *= cr1;

        // ---- O += P V ;  l += P * ones (P packed inline) ----
#pragma unroll
        for (int ks = 0; ks < 4; ++ks) {
            uint32_t pa[4];
            pa[0] = pack_h2(ex2f(s[2*ks][0]   - mn0), ex2f(s[2*ks][1]   - mn0));
            pa[1] = pack_h2(ex2f(s[2*ks][2]   - mn1), ex2f(s[2*ks][3]   - mn1));
            pa[2] = pack_h2(ex2f(s[2*ks+1][0] - mn0), ex2f(s[2*ks+1][1] - mn0));
            pa[3] = pack_h2(ex2f(s[2*ks+1][2] - mn1), ex2f(s[2*ks+1][3] - mn1));
            MMA_F16(ol, pa, ONES_H2, ONES_H2);
#pragma unroll
            for (int db = 0; db < 4; ++db) {
                uint32_t vb4[4];
                LDSM_X4_T(vb4, stg + vBrel + ks * 16 * APITCH + db * 32);
                MMA_F16(o[2*db],   pa, vb4[0], vb4[1]);
                MMA_F16(o[2*db+1], pa, vb4[2], vb4[3]);
            }
        }
    }

    // ---- epilogue: add sink to l, normalize, plain fp16 store ----
    const float l0 = ol[0] + ex2f(snk2 - m0);
    const float l1 = ol[2] + ex2f(snk2 - m1);
    const float i0 = 1.f / l0, i1 = 1.f / l1;
#pragma unroll
    for (int nf = 0; nf < 8; ++nf) {
        const int col = h * HDd + nf * 8 + tig * 2;
        {
            size_t idx = ((size_t)(b * Ss + r0g)) * Dd + col;
            *(uint32_t*)&aoh[idx] = pack_h2(o[nf][0] * i0, o[nf][1] * i0);
        }
        {
            size_t idx = ((size_t)(b * Ss + r1g)) * Dd + col;
            *(uint32_t*)&aoh[idx] = pack_h2(o[nf][2] * i1, o[nf][3] * i1);
        }
    }
}

// =================================================================
extern "C" void kernel_launch(void* const* d_in, const int* in_sizes, int n_in,
                              void* d_out, int out_size) {
    const float* x  = (const float*)d_in[0];
    const float* wq = (const float*)d_in[1];
    const float* wk = (const float*)d_in[2];
    const float* wv = (const float*)d_in[3];
    const float* wo = (const float*)d_in[4];
    const float* qw = (const float*)d_in[5];
    const float* kw = (const float*)d_in[6];
    const float* sk = (const float*)d_in[7];
    float* out = (float*)d_out;

    uint16_t *xh, *wh, *woh;
    uint16_t *qhp, *khp, *vhp, *aoh;
    float *cosT, *sinT;
    cudaGetSymbolAddress((void**)&xh,  g_xh);
    cudaGetSymbolAddress((void**)&wh,  g_wh);
    cudaGetSymbolAddress((void**)&woh, g_woh);
    cudaGetSymbolAddress((void**)&qhp, g_qh);
    cudaGetSymbolAddress((void**)&khp, g_kh);
    cudaGetSymbolAddress((void**)&vhp, g_vh);
    cudaGetSymbolAddress((void**)&aoh, g_aoh);
    cudaGetSymbolAddress((void**)&cosT, g_cosT);
    cudaGetSymbolAddress((void**)&sinT, g_sinT);

    cudaFuncSetAttribute(gemm_qkv, cudaFuncAttributeMaxDynamicSharedMemorySize,
                         GEMM1_SMEM);
    cudaFuncSetAttribute(gemm_out, cudaFuncAttributeMaxDynamicSharedMemorySize,
                         GEMM1_SMEM);
    cudaFuncSetAttribute(attn_tc, cudaFuncAttributeMaxDynamicSharedMemorySize,
                         ATTN_SMEM);

    // converts (8192 blocks) + rope tables (256 blocks)
    cvt_all<<<8448, 256>>>((const float4*)x, (const float4*)wq,
                           (const float4*)wk, (const float4*)wv,
                           (const float4*)wo,
                           (uint2*)xh, (uint2*)wh, (uint2*)woh, cosT, sinT);

    // QKV projection + fused norm/rope (tile 256x128, 1 CTA/SM)
    gemm_qkv<<<dim3(3072 / 128, Mrows / 256), 256, GEMM1_SMEM>>>(
        xh, wh, qw, kw, cosT, sinT, qhp, khp, vhp);

    // flash attention (Q/K/V all plain)
    attn_tc<<<dim3(Ss / 128, Bb * Hh), 256, ATTN_SMEM>>>(
        qhp, khp, vhp, sk, aoh);

    // output projection (tile 256x128, 128 CTAs = sub-1-wave)
    gemm_out<<<dim3(Dd / 128, Mrows / 256), 256, GEMM1_SMEM>>>(
        aoh, woh, out);
}

// round 15
// speedup vs baseline: 1.6245x; 1.6245x over previous
#include <cuda_runtime.h>
#include <cuda_fp16.h>
#include <stdint.h>
#include <math.h>

// Problem constants
#define Bb   2
#define Ss   2048
#define Dd   1024
#define Hh   16
#define HDd  64
#define Mrows (Bb*Ss)   // 4096

#define SC2 0.18033688011112042f   // 0.125 * log2(e), folded into Q
#define LOG2E 1.4426950408889634f

// ---------------- scratch (no allocs allowed) ----------------
__device__ uint16_t g_xh [Mrows * Dd];            // x fp16 (plain)
__device__ uint16_t g_wh [3072 * Dd];             // fused wq|wk|wv fp16
__device__ uint16_t g_woh[Dd * Dd];               // wo fp16
__device__ uint16_t g_qh [Mrows * Dd];            // [B,H,S,64] fp16 (pre-scaled)
__device__ uint16_t g_kh [Mrows * Dd];            // fp16
__device__ uint16_t g_vh [Mrows * Dd];            // fp16 (plain)
__device__ uint16_t g_aoh[Mrows * Dd];            // attn out fp16 (plain)
__device__ float    g_cosT[Ss * 32];              // rope tables
__device__ float    g_sinT[Ss * 32];

// ================= PTX helpers ==========================
__device__ __forceinline__ uint32_t smem_u32(const void* p) {
    uint32_t a;
    asm("{ .reg .u64 t; cvta.to.shared.u64 t, %1; cvt.u32.u64 %0, t; }"
        : "=r"(a) : "l"(p));
    return a;
}
__device__ __forceinline__ void cp_async16(uint32_t s, const void* g) {
    asm volatile("cp.async.cg.shared.global [%0], [%1], 16;" :: "r"(s), "l"(g));
}
#define CP_COMMIT() asm volatile("cp.async.commit_group;" ::: "memory")
#define CP_WAIT(n)  asm volatile("cp.async.wait_group %0;" :: "n"(n) : "memory")

#define LDSM_X4(r, addr) \
    asm volatile("ldmatrix.sync.aligned.m8n8.x4.shared.b16 {%0,%1,%2,%3}, [%4];" \
        : "=r"((r)[0]), "=r"((r)[1]), "=r"((r)[2]), "=r"((r)[3]) : "r"(addr))
#define LDSM_X4_T(r, addr) \
    asm volatile("ldmatrix.sync.aligned.m8n8.x4.trans.shared.b16 {%0,%1,%2,%3}, [%4];" \
        : "=r"((r)[0]), "=r"((r)[1]), "=r"((r)[2]), "=r"((r)[3]) : "r"(addr))

#define MMA_F16(d, a, b0, b1) \
    asm volatile("mma.sync.aligned.m16n8k16.row.col.f32.f16.f16.f32 " \
        "{%0,%1,%2,%3}, {%4,%5,%6,%7}, {%8,%9}, {%0,%1,%2,%3};" \
        : "+f"((d)[0]), "+f"((d)[1]), "+f"((d)[2]), "+f"((d)[3]) \
        : "r"((a)[0]), "r"((a)[1]), "r"((a)[2]), "r"((a)[3]), \
          "r"(b0), "r"(b1))

__device__ __forceinline__ uint32_t pack_h2(float a, float b) {
    uint32_t r;
    asm("cvt.rn.f16x2.f32 %0, %1, %2;" : "=r"(r) : "f"(b), "f"(a));
    return r;
}
__device__ __forceinline__ float ex2f(float x) {
    float y;
    asm("ex2.approx.f32 %0, %1;" : "=f"(y) : "f"(x));
    return y;
}

// =================================================================
// fused convert: x, w, wo -> plain fp16 ; rope tables in own blocks
// =================================================================
__global__ __launch_bounds__(256)
void cvt_all(const float4* __restrict__ x,  const float4* __restrict__ wq,
             const float4* __restrict__ wk, const float4* __restrict__ wv,
             const float4* __restrict__ wo,
             uint2* __restrict__ xh, uint2* __restrict__ wh,
             uint2* __restrict__ woh,
             float* __restrict__ cosT, float* __restrict__ sinT) {
    int i = blockIdx.x * 256 + threadIdx.x;
    if (i >= 2097152) {   // rope-table blocks
        int t = i - 2097152;
        if (t < 65536) {
            int s = t >> 5, j = t & 31;
            float inv = exp2f(-(float)j * 0.4152410118609203f); // log2(1e4)/32
            float sn, cs;
            sincosf((float)s * inv, &sn, &cs);
            cosT[t] = cs;
            sinT[t] = sn;
        }
        return;
    }
    const float4* src;
    uint2* dst;
    if (i < 1048576) {
        src = x + i; dst = xh + i;
    } else {
        int i2 = i - 1048576;
        int reg = i2 >> 18;            // 0..3
        int off = i2 & 262143;
        if (reg == 0)      { src = wq + off; dst = wh + off; }
        else if (reg == 1) { src = wk + off; dst = wh + 262144 + off; }
        else if (reg == 2) { src = wv + off; dst = wh + 524288 + off; }
        else               { src = wo + off; dst = woh + off; }
    }
    float4 v = *src;
    uint2 o;
    o.x = pack_h2(v.x, v.y);
    o.y = pack_h2(v.z, v.w);
    *dst = o;
}

// =================================================================
// GEMM framework (R13 proven): plain fp16 HMMA, tile 128x128x64,
// 256 thr, warps 4(M)x2(N), warp 32x64, 3-stage ring, 2 CTAs/SM.
// =================================================================
#define GK 1024
#define GPITCH 144                // 64 f16 = 128B + 16B pad
#define P_A  0                    // 128*144 = 18432
#define P_B  18432
#define P_STG 36864
#define GEMM1_SMEM (3 * P_STG)    // 110592

#define GEMM_PREAMBLE                                                        \
    extern __shared__ char smem[];                                           \
    const uint32_t sb = smem_u32(smem);                                      \
    const int tid = threadIdx.x;                                             \
    const int wid = tid >> 5, lane = tid & 31;                               \
    const int wm = wid & 3, wn = wid >> 2;                                   \
    const int gid = lane >> 2, tig = lane & 3;                               \
    const int bm = blockIdx.y * 128, bn = blockIdx.x * 128;                  \
    uint32_t aAddr[2], bAddr[4];                                             \
    _Pragma("unroll")                                                        \
    for (int mf = 0; mf < 2; ++mf)                                           \
        aAddr[mf] = (wm * 32 + mf * 16 + (lane & 15)) * GPITCH               \
                    + (lane >> 4) * 16;                                      \
    _Pragma("unroll")                                                        \
    for (int nb = 0; nb < 4; ++nb)                                           \
        bAddr[nb] = (wn * 64 + nb * 16 + ((lane >> 4) << 3)                  \
                    + (lane & 7)) * GPITCH + ((lane >> 3) & 1) * 16;         \
    float acc[2][8][4];                                                      \
    _Pragma("unroll")                                                        \
    for (int i = 0; i < 2; ++i)                                              \
        _Pragma("unroll")                                                    \
        for (int j = 0; j < 8; ++j)                                          \
            _Pragma("unroll")                                                \
            for (int c = 0; c < 4; ++c) acc[i][j][c] = 0.f;

__device__ __forceinline__ void gemm1_issue(
    uint32_t stg, const uint16_t* __restrict__ A,
    const uint16_t* __restrict__ B, int bm, int bn, int k0, int tid) {
#pragma unroll
    for (int u = 0; u < 4; ++u) {
        int q = tid + u * 256;          // 0..1023
        int r = q >> 3, c = q & 7;
        uint32_t d = r * GPITCH + c * 16;
        cp_async16(stg + P_A + d, A + (size_t)(bm + r) * GK + k0 + c * 8);
        cp_async16(stg + P_B + d, B + (size_t)(bn + r) * GK + k0 + c * 8);
    }
}

#define GEMM1_MAINLOOP(A, B, bm, bn)                                         \
    gemm1_issue(sb, A, B, bm, bn, 0, tid);                                   \
    CP_COMMIT();                                                             \
    gemm1_issue(sb + P_STG, A, B, bm, bn, 64, tid);                          \
    CP_COMMIT();                                                             \
    for (int s = 0; s < 16; ++s) {                                           \
        if (s < 15) { CP_WAIT(1); } else { CP_WAIT(0); }                     \
        __syncthreads();                                                     \
        if (s + 2 < 16) {                                                    \
            gemm1_issue(sb + ((s + 2) % 3) * P_STG, A, B,                    \
                        bm, bn, (s + 2) * 64, tid);                          \
            CP_COMMIT();                                                     \
        }                                                                    \
        const uint32_t stg = sb + (s % 3) * P_STG;                           \
        _Pragma("unroll")                                                    \
        for (int ks = 0; ks < 4; ++ks) {                                     \
            uint32_t bh4[4][4];                                              \
            _Pragma("unroll")                                                \
            for (int nb = 0; nb < 4; ++nb)                                   \
                LDSM_X4(bh4[nb], stg + P_B + bAddr[nb] + ks * 32);           \
            _Pragma("unroll")                                                \
            for (int mf = 0; mf < 2; ++mf) {                                 \
                uint32_t ah[4];                                              \
                LDSM_X4(ah, stg + P_A + aAddr[mf] + ks * 32);                \
                _Pragma("unroll")                                            \
                for (int nb = 0; nb < 4; ++nb) {                             \
                    MMA_F16(acc[mf][2*nb],   ah, bh4[nb][0], bh4[nb][1]);    \
                    MMA_F16(acc[mf][2*nb+1], ah, bh4[nb][2], bh4[nb][3]);    \
                }                                                            \
            }                                                                \
        }                                                                    \
    }

// =================================================================
// QKV GEMM (A plain) with fused RMSNorm+RoPE epilogue.
// =================================================================
__global__ __launch_bounds__(256, 2)
void gemm_qkv(const uint16_t* __restrict__ A, const uint16_t* __restrict__ B,
              const float* __restrict__ qw, const float* __restrict__ kw,
              const float* __restrict__ cosT, const float* __restrict__ sinT,
              uint16_t* __restrict__ qh, uint16_t* __restrict__ kh,
              uint16_t* __restrict__ vh) {
    GEMM_PREAMBLE
    GEMM1_MAINLOOP(A, B, bm, bn)

    const int cb = bn + wn * 64;
    const int sect = cb >> 10;          // 0=Q, 1=K, 2=V
    const int hh = (cb >> 6) & 15;

#pragma unroll
    for (int mf = 0; mf < 2; ++mf) {
#pragma unroll
        for (int hf = 0; hf < 2; ++hf) {
            const int row = bm + wm * 32 + mf * 16 + gid + hf * 8;
            const int s = row & (Ss - 1);
            const int b = row >> 11;
            const size_t dst = (((size_t)(b * Hh + hh)) * Ss + s) * HDd;
            float v[8][2];
#pragma unroll
            for (int nf = 0; nf < 8; ++nf) {
                v[nf][0] = acc[mf][nf][hf * 2];
                v[nf][1] = acc[mf][nf][hf * 2 + 1];
            }
            if (sect == 2) {   // V: plain fp16
#pragma unroll
                for (int nf = 0; nf < 8; ++nf) {
                    int d0 = nf * 8 + tig * 2;
                    *(uint32_t*)&vh[dst + d0] = pack_h2(v[nf][0], v[nf][1]);
                }
            } else {           // Q or K: rms + rope, plain fp16
                float ss = 0.f;
#pragma unroll
                for (int nf = 0; nf < 8; ++nf)
                    ss += v[nf][0] * v[nf][0] + v[nf][1] * v[nf][1];
                ss += __shfl_xor_sync(0xffffffffu, ss, 1);
                ss += __shfl_xor_sync(0xffffffffu, ss, 2);
                float r = rsqrtf(ss * (1.0f / 64.0f) + 1e-6f);
                const float* w = sect ? kw : qw;
                uint16_t* outp = sect ? kh : qh;
                if (sect == 0) r *= SC2;   // fold softmax scale into Q
#pragma unroll
                for (int nf = 0; nf < 4; ++nf) {
                    int d0 = nf * 8 + tig * 2;
                    float2 w1 = *(const float2*)&w[d0];
                    float2 w2 = *(const float2*)&w[d0 + 32];
                    float2 cs = *(const float2*)&cosT[s * 32 + d0];
                    float2 sn = *(const float2*)&sinT[s * 32 + d0];
                    float x1a = v[nf][0]     * r * w1.x;
                    float x1b = v[nf][1]     * r * w1.y;
                    float x2a = v[nf + 4][0] * r * w2.x;
                    float x2b = v[nf + 4][1] * r * w2.y;
                    float o1a = x1a * cs.x - x2a * sn.x;
                    float o1b = x1b * cs.y - x2b * sn.y;
                    float o2a = x2a * cs.x + x1a * sn.x;
                    float o2b = x2b * cs.y + x1b * sn.y;
                    *(uint32_t*)&outp[dst + d0]      = pack_h2(o1a, o1b);
                    *(uint32_t*)&outp[dst + d0 + 32] = pack_h2(o2a, o2b);
                }
            }
        }
    }
}

// =================================================================
// Output-projection GEMM (A plain fp16, fp32 C)
// =================================================================
__global__ __launch_bounds__(256, 2)
void gemm_out(const uint16_t* __restrict__ A, const uint16_t* __restrict__ B,
              float* __restrict__ C) {
    GEMM_PREAMBLE
    GEMM1_MAINLOOP(A, B, bm, bn)
#pragma unroll
    for (int mf = 0; mf < 2; ++mf) {
        const int row = bm + wm * 32 + mf * 16 + gid;
#pragma unroll
        for (int nf = 0; nf < 8; ++nf) {
            const int col = bn + wn * 64 + nf * 8 + tig * 2;
            *(float2*)&C[(size_t)row * Dd + col] =
                make_float2(acc[mf][nf][0], acc[mf][nf][1]);
            *(float2*)&C[(size_t)(row + 8) * Dd + col] =
                make_float2(acc[mf][nf][2], acc[mf][nf][3]);
        }
    }
}

// =================================================================
// fp16 flash attention: Q plain (pre-scaled, frags hoisted), K/V plain.
// Br=128, Bc=64, 256 threads, 4-stage KV ring, 2 CTAs/SM.
// =================================================================
#define APITCH 144
#define A_Q  0
#define A_QSZ 18432               // 128*144
#define A_K  0
#define A_V  9216
#define A_STG 18432
#define ATTN_SMEM (A_QSZ + 4 * A_STG)   // 92160
#define ONES_H2 0x3C003C00u

__device__ __forceinline__ void attn_kv_issue(
    uint32_t stg, const uint16_t* __restrict__ kh,
    const uint16_t* __restrict__ vh, size_t seqbase, int j, int tid) {
#pragma unroll
    for (int u = 0; u < 2; ++u) {
        int q = tid + u * 256;          // 0..511
        int r = q >> 3, c = q & 7;
        size_t src = seqbase + (size_t)(j * 64 + r) * 64 + c * 8;
        uint32_t d = r * APITCH + c * 16;
        cp_async16(stg + A_K + d, kh + src);
        cp_async16(stg + A_V + d, vh + src);
    }
}

__global__ __launch_bounds__(256, 2)
void attn_tc(const uint16_t* __restrict__ qh,
             const uint16_t* __restrict__ kh, const uint16_t* __restrict__ vh,
             const float* __restrict__ sinkl,
             uint16_t* __restrict__ aoh) {
    extern __shared__ char smem[];
    const uint32_t sb = smem_u32(smem);
    const int tid = threadIdx.x;
    const int wid = tid >> 5, lane = tid & 31;
    const int gid = lane >> 2, tig = lane & 3;
    const int qb = gridDim.x - 1 - blockIdx.x;   // heavy tiles first
    const int bh = blockIdx.y;
    const int h  = bh & (Hh - 1);
    const int b  = bh >> 4;
    const size_t seqbase = (size_t)bh * Ss * HDd;
    const int q0 = qb * 128;
    const int jmax = 2 * qb + 1;

    // ---- prologue: Q tile (plain) + KV stages 0,1,2 ----
#pragma unroll
    for (int u = 0; u < 2; ++u) {
        int q = tid + u * 256;              // 0..511
        int r = q >> 2, c = q & 3;          // 128 rows x 4 chunks
        size_t src = seqbase + (size_t)(q0 + r) * 64 + c * 16;
        uint32_t d = r * APITCH + c * 32;
        cp_async16(sb + A_Q + d, qh + src);
        cp_async16(sb + A_Q + d + 16, qh + src + 8);
    }
    attn_kv_issue(sb + A_QSZ, kh, vh, seqbase, 0, tid);
    CP_COMMIT();
    if (1 <= jmax) {
        attn_kv_issue(sb + A_QSZ + A_STG, kh, vh, seqbase, 1, tid);
    }
    CP_COMMIT();
    if (2 <= jmax) {
        attn_kv_issue(sb + A_QSZ + 2 * A_STG, kh, vh, seqbase, 2, tid);
    }
    CP_COMMIT();

    const uint32_t qA = sb + A_Q + (wid * 16 + (lane & 15)) * APITCH
                        + (lane >> 4) * 16;
    uint32_t kB[4];
#pragma unroll
    for (int nb = 0; nb < 4; ++nb)
        kB[nb] = A_K + (nb * 16 + ((lane >> 4) << 3) + (lane & 7)) * APITCH
                 + ((lane >> 3) & 1) * 16;
    const uint32_t vBrel = A_V + (lane & 15) * APITCH + (lane >> 4) * 16;

    const float snk2 = sinkl[h] * LOG2E;
    float m0 = snk2, m1 = snk2;
    float o[8][4], ol[4];
#pragma unroll
    for (int i = 0; i < 8; ++i)
#pragma unroll
        for (int c = 0; c < 4; ++c) o[i][c] = 0.f;
#pragma unroll
    for (int c = 0; c < 4; ++c) ol[c] = 0.f;

    const int r0g = q0 + wid * 16 + gid;
    const int r1g = r0g + 8;

    uint32_t qf[4][4];   // hoisted Q fragments (loaded at j==0)

    for (int j = 0; j <= jmax; ++j) {
        if (j + 2 <= jmax)      { CP_WAIT(2); }
        else if (j + 1 <= jmax) { CP_WAIT(1); }
        else                    { CP_WAIT(0); }
        __syncthreads();
        if (j + 3 <= jmax) {
            attn_kv_issue(sb + A_QSZ + ((j + 3) & 3) * A_STG,
                          kh, vh, seqbase, j + 3, tid);
            CP_COMMIT();
        }
        const uint32_t stg = sb + A_QSZ + (j & 3) * A_STG;

        if (j == 0) {   // Q arrived with KV stage 0; load frags once
#pragma unroll
            for (int ks = 0; ks < 4; ++ks)
                LDSM_X4(qf[ks], qA + ks * 32);
        }

        // ---- S = Q K^T (both plain fp16, Q pre-scaled) ----
        float s[8][4];
#pragma unroll
        for (int i = 0; i < 8; ++i)
#pragma unroll
            for (int c = 0; c < 4; ++c) s[i][c] = 0.f;

#pragma unroll
        for (int ks = 0; ks < 4; ++ks) {
#pragma unroll
            for (int nb = 0; nb < 4; ++nb) {
                uint32_t kb4[4];
                LDSM_X4(kb4, stg + kB[nb] + ks * 32);
                MMA_F16(s[2*nb],   qf[ks], kb4[0], kb4[1]);
                MMA_F16(s[2*nb+1], qf[ks], kb4[2], kb4[3]);
            }
        }

        // ---- causal mask (diagonal blocks only) ----
        if (j >= 2 * qb) {
#pragma unroll
            for (int nf = 0; nf < 8; ++nf)
#pragma unroll
                for (int c = 0; c < 4; ++c) {
                    int col = j * 64 + nf * 8 + tig * 2 + (c & 1);
                    int row = (c < 2) ? r0g : r1g;
                    if (col > row) s[nf][c] = -1e30f;
                }
        }

        // ---- online softmax (base-2) ----
        float mx0 = -1e30f, mx1 = -1e30f;
#pragma unroll
        for (int nf = 0; nf < 8; ++nf) {
            mx0 = fmaxf(mx0, fmaxf(s[nf][0], s[nf][1]));
            mx1 = fmaxf(mx1, fmaxf(s[nf][2], s[nf][3]));
        }
        mx0 = fmaxf(mx0, __shfl_xor_sync(0xffffffffu, mx0, 1));
        mx0 = fmaxf(mx0, __shfl_xor_sync(0xffffffffu, mx0, 2));
        mx1 = fmaxf(mx1, __shfl_xor_sync(0xffffffffu, mx1, 1));
        mx1 = fmaxf(mx1, __shfl_xor_sync(0xffffffffu, mx1, 2));
        const float mn0 = fmaxf(m0, mx0), mn1 = fmaxf(m1, mx1);
        const float cr0 = ex2f(m0 - mn0), cr1 = ex2f(m1 - mn1);
        m0 = mn0; m1 = mn1;
#pragma unroll
        for (int nf = 0; nf < 8; ++nf) {
            o[nf][0] *= cr0; o[nf][1] *= cr0;
            o[nf][2] *= cr1; o[nf][3] *= cr1;
        }
        ol[0] *= cr0; ol[1] *= cr0; ol[2] *= cr1; ol[3] *= cr1;

        // ---- O += P V ;  l += P * ones (P packed inline) ----
#pragma unroll
        for (int ks = 0; ks < 4; ++ks) {
            uint32_t pa[4];
            pa[0] = pack_h2(ex2f(s[2*ks][0]   - mn0), ex2f(s[2*ks][1]   - mn0));
            pa[1] = pack_h2(ex2f(s[2*ks][2]   - mn1), ex2f(s[2*ks][3]   - mn1));
            pa[2] = pack_h2(ex2f(s[2*ks+1][0] - mn0), ex2f(s[2*ks+1][1] - mn0));
            pa[3] = pack_h2(ex2f(s[2*ks+1][2] - mn1), ex2f(s[2*ks+1][3] - mn1));
            MMA_F16(ol, pa, ONES_H2, ONES_H2);
#pragma unroll
            for (int db = 0; db < 4; ++db) {
                uint32_t vb4[4];
                LDSM_X4_T(vb4, stg + vBrel + ks * 16 * APITCH + db * 32);
                MMA_F16(o[2*db],   pa, vb4[0], vb4[1]);
                MMA_F16(o[2*db+1], pa, vb4[2], vb4[3]);
            }
        }
    }

    // ---- epilogue: add sink to l, normalize, plain fp16 store ----
    const float l0 = ol[0] + ex2f(snk2 - m0);
    const float l1 = ol[2] + ex2f(snk2 - m1);
    const float i0 = 1.f / l0, i1 = 1.f / l1;
#pragma unroll
    for (int nf = 0; nf < 8; ++nf) {
        const int col = h * HDd + nf * 8 + tig * 2;
        {
            size_t idx = ((size_t)(b * Ss + r0g)) * Dd + col;
            *(uint32_t*)&aoh[idx] = pack_h2(o[nf][0] * i0, o[nf][1] * i0);
        }
        {
            size_t idx = ((size_t)(b * Ss + r1g)) * Dd + col;
            *(uint32_t*)&aoh[idx] = pack_h2(o[nf][2] * i1, o[nf][3] * i1);
        }
    }
}

// =================================================================
extern "C" void kernel_launch(void* const* d_in, const int* in_sizes, int n_in,
                              void* d_out, int out_size) {
    const float* x  = (const float*)d_in[0];
    const float* wq = (const float*)d_in[1];
    const float* wk = (const float*)d_in[2];
    const float* wv = (const float*)d_in[3];
    const float* wo = (const float*)d_in[4];
    const float* qw = (const float*)d_in[5];
    const float* kw = (const float*)d_in[6];
    const float* sk = (const float*)d_in[7];
    float* out = (float*)d_out;

    uint16_t *xh, *wh, *woh;
    uint16_t *qhp, *khp, *vhp, *aoh;
    float *cosT, *sinT;
    cudaGetSymbolAddress((void**)&xh,  g_xh);
    cudaGetSymbolAddress((void**)&wh,  g_wh);
    cudaGetSymbolAddress((void**)&woh, g_woh);
    cudaGetSymbolAddress((void**)&qhp, g_qh);
    cudaGetSymbolAddress((void**)&khp, g_kh);
    cudaGetSymbolAddress((void**)&vhp, g_vh);
    cudaGetSymbolAddress((void**)&aoh, g_aoh);
    cudaGetSymbolAddress((void**)&cosT, g_cosT);
    cudaGetSymbolAddress((void**)&sinT, g_sinT);

    cudaFuncSetAttribute(gemm_qkv, cudaFuncAttributeMaxDynamicSharedMemorySize,
                         GEMM1_SMEM);
    cudaFuncSetAttribute(gemm_out, cudaFuncAttributeMaxDynamicSharedMemorySize,
                         GEMM1_SMEM);
    cudaFuncSetAttribute(attn_tc, cudaFuncAttributeMaxDynamicSharedMemorySize,
                         ATTN_SMEM);

    // converts (8192 blocks) + rope tables (256 blocks)
    cvt_all<<<8448, 256>>>((const float4*)x, (const float4*)wq,
                           (const float4*)wk, (const float4*)wv,
                           (const float4*)wo,
                           (uint2*)xh, (uint2*)wh, (uint2*)woh, cosT, sinT);

    // QKV projection + fused norm/rope (128x128 tile, 2 CTAs/SM)
    gemm_qkv<<<dim3(3072 / 128, Mrows / 128), 256, GEMM1_SMEM>>>(
        xh, wh, qw, kw, cosT, sinT, qhp, khp, vhp);

    // flash attention (Q/K/V plain, Q frags hoisted)
    attn_tc<<<dim3(Ss / 128, Bb * Hh), 256, ATTN_SMEM>>>(
        qhp, khp, vhp, sk, aoh);

    // output projection (128x128 tile, 2 CTAs/SM)
    gemm_out<<<dim3(Dd / 128, Mrows / 128), 256, GEMM1_SMEM>>>(
        aoh, woh, out);
}

// round 16
// speedup vs baseline: 1.6400x; 1.0095x over previous
#include <cuda_runtime.h>
#include <cuda_fp16.h>
#include <stdint.h>
#include <math.h>

// Problem constants
#define Bb   2
#define Ss   2048
#define Dd   1024
#define Hh   16
#define HDd  64
#define Mrows (Bb*Ss)   // 4096

#define SC2 0.18033688011112042f   // 0.125 * log2(e), folded into Q
#define LOG2E 1.4426950408889634f

// ---------------- scratch (no allocs allowed) ----------------
__device__ uint16_t g_xh [Mrows * Dd];            // x fp16 (plain)
__device__ uint16_t g_wh [3072 * Dd];             // fused wq|wk|wv fp16
__device__ uint16_t g_woh[Dd * Dd];               // wo fp16
__device__ uint16_t g_qh [Mrows * Dd];            // [B,H,S,64] fp16 (pre-scaled)
__device__ uint16_t g_kh [Mrows * Dd];            // fp16
__device__ uint16_t g_vh [Mrows * Dd];            // fp16 (plain)
__device__ uint16_t g_aoh[Mrows * Dd];            // attn out fp16 (plain)
__device__ float    g_cosT[Ss * 32];              // rope tables
__device__ float    g_sinT[Ss * 32];

// ================= PTX helpers ==========================
__device__ __forceinline__ uint32_t smem_u32(const void* p) {
    uint32_t a;
    asm("{ .reg .u64 t; cvta.to.shared.u64 t, %1; cvt.u32.u64 %0, t; }"
        : "=r"(a) : "l"(p));
    return a;
}
__device__ __forceinline__ void cp_async16(uint32_t s, const void* g) {
    asm volatile("cp.async.cg.shared.global [%0], [%1], 16;" :: "r"(s), "l"(g));
}
#define CP_COMMIT() asm volatile("cp.async.commit_group;" ::: "memory")
#define CP_WAIT(n)  asm volatile("cp.async.wait_group %0;" :: "n"(n) : "memory")

#define LDSM_X4(r, addr) \
    asm volatile("ldmatrix.sync.aligned.m8n8.x4.shared.b16 {%0,%1,%2,%3}, [%4];" \
        : "=r"((r)[0]), "=r"((r)[1]), "=r"((r)[2]), "=r"((r)[3]) : "r"(addr))
#define LDSM_X4_T(r, addr) \
    asm volatile("ldmatrix.sync.aligned.m8n8.x4.trans.shared.b16 {%0,%1,%2,%3}, [%4];" \
        : "=r"((r)[0]), "=r"((r)[1]), "=r"((r)[2]), "=r"((r)[3]) : "r"(addr))

#define MMA_F16(d, a, b0, b1) \
    asm volatile("mma.sync.aligned.m16n8k16.row.col.f32.f16.f16.f32 " \
        "{%0,%1,%2,%3}, {%4,%5,%6,%7}, {%8,%9}, {%0,%1,%2,%3};" \
        : "+f"((d)[0]), "+f"((d)[1]), "+f"((d)[2]), "+f"((d)[3]) \
        : "r"((a)[0]), "r"((a)[1]), "r"((a)[2]), "r"((a)[3]), \
          "r"(b0), "r"(b1))

__device__ __forceinline__ uint32_t pack_h2(float a, float b) {
    uint32_t r;
    asm("cvt.rn.f16x2.f32 %0, %1, %2;" : "=r"(r) : "f"(b), "f"(a));
    return r;
}
__device__ __forceinline__ float ex2f(float x) {
    float y;
    asm("ex2.approx.f32 %0, %1;" : "=f"(y) : "f"(x));
    return y;
}
// packed fp16x2 exp2: input two log2-domain values, output two fp16 P's
__device__ __forceinline__ uint32_t ex2_h2(uint32_t x) {
    uint32_t y;
    asm("ex2.approx.f16x2 %0, %1;" : "=r"(y) : "r"(x));
    return y;
}

// =================================================================
// fused convert: x, w, wo -> plain fp16 ; rope tables in own blocks
// =================================================================
__global__ __launch_bounds__(256)
void cvt_all(const float4* __restrict__ x,  const float4* __restrict__ wq,
             const float4* __restrict__ wk, const float4* __restrict__ wv,
             const float4* __restrict__ wo,
             uint2* __restrict__ xh, uint2* __restrict__ wh,
             uint2* __restrict__ woh,
             float* __restrict__ cosT, float* __restrict__ sinT) {
    int i = blockIdx.x * 256 + threadIdx.x;
    if (i >= 2097152) {   // rope-table blocks
        int t = i - 2097152;
        if (t < 65536) {
            int s = t >> 5, j = t & 31;
            float inv = exp2f(-(float)j * 0.4152410118609203f); // log2(1e4)/32
            float sn, cs;
            sincosf((float)s * inv, &sn, &cs);
            cosT[t] = cs;
            sinT[t] = sn;
        }
        return;
    }
    const float4* src;
    uint2* dst;
    if (i < 1048576) {
        src = x + i; dst = xh + i;
    } else {
        int i2 = i - 1048576;
        int reg = i2 >> 18;            // 0..3
        int off = i2 & 262143;
        if (reg == 0)      { src = wq + off; dst = wh + off; }
        else if (reg == 1) { src = wk + off; dst = wh + 262144 + off; }
        else if (reg == 2) { src = wv + off; dst = wh + 524288 + off; }
        else               { src = wo + off; dst = woh + off; }
    }
    float4 v = *src;
    uint2 o;
    o.x = pack_h2(v.x, v.y);
    o.y = pack_h2(v.z, v.w);
    *dst = o;
}

// =================================================================
// GEMM framework (proven): plain fp16 HMMA, tile 128x128x64,
// 256 thr, warps 4(M)x2(N), warp 32x64, 3-stage ring, 2 CTAs/SM.
// =================================================================
#define GK 1024
#define GPITCH 144                // 64 f16 = 128B + 16B pad
#define P_A  0                    // 128*144 = 18432
#define P_B  18432
#define P_STG 36864
#define GEMM1_SMEM (3 * P_STG)    // 110592

#define GEMM_PREAMBLE                                                        \
    extern __shared__ char smem[];                                           \
    const uint32_t sb = smem_u32(smem);                                      \
    const int tid = threadIdx.x;                                             \
    const int wid = tid >> 5, lane = tid & 31;                               \
    const int wm = wid & 3, wn = wid >> 2;                                   \
    const int gid = lane >> 2, tig = lane & 3;                               \
    const int bm = blockIdx.y * 128, bn = blockIdx.x * 128;                  \
    uint32_t aAddr[2], bAddr[4];                                             \
    _Pragma("unroll")                                                        \
    for (int mf = 0; mf < 2; ++mf)                                           \
        aAddr[mf] = (wm * 32 + mf * 16 + (lane & 15)) * GPITCH               \
                    + (lane >> 4) * 16;                                      \
    _Pragma("unroll")                                                        \
    for (int nb = 0; nb < 4; ++nb)                                           \
        bAddr[nb] = (wn * 64 + nb * 16 + ((lane >> 4) << 3)                  \
                    + (lane & 7)) * GPITCH + ((lane >> 3) & 1) * 16;         \
    float acc[2][8][4];                                                      \
    _Pragma("unroll")                                                        \
    for (int i = 0; i < 2; ++i)                                              \
        _Pragma("unroll")                                                    \
        for (int j = 0; j < 8; ++j)                                          \
            _Pragma("unroll")                                                \
            for (int c = 0; c < 4; ++c) acc[i][j][c] = 0.f;

__device__ __forceinline__ void gemm1_issue(
    uint32_t stg, const uint16_t* __restrict__ A,
    const uint16_t* __restrict__ B, int bm, int bn, int k0, int tid) {
#pragma unroll
    for (int u = 0; u < 4; ++u) {
        int q = tid + u * 256;          // 0..1023
        int r = q >> 3, c = q & 7;
        uint32_t d = r * GPITCH + c * 16;
        cp_async16(stg + P_A + d, A + (size_t)(bm + r) * GK + k0 + c * 8);
        cp_async16(stg + P_B + d, B + (size_t)(bn + r) * GK + k0 + c * 8);
    }
}

#define GEMM1_MAINLOOP(A, B, bm, bn)                                         \
    gemm1_issue(sb, A, B, bm, bn, 0, tid);                                   \
    CP_COMMIT();                                                             \
    gemm1_issue(sb + P_STG, A, B, bm, bn, 64, tid);                          \
    CP_COMMIT();                                                             \
    for (int s = 0; s < 16; ++s) {                                           \
        if (s < 15) { CP_WAIT(1); } else { CP_WAIT(0); }                     \
        __syncthreads();                                                     \
        if (s + 2 < 16) {                                                    \
            gemm1_issue(sb + ((s + 2) % 3) * P_STG, A, B,                    \
                        bm, bn, (s + 2) * 64, tid);                          \
            CP_COMMIT();                                                     \
        }                                                                    \
        const uint32_t stg = sb + (s % 3) * P_STG;                           \
        _Pragma("unroll")                                                    \
        for (int ks = 0; ks < 4; ++ks) {                                     \
            uint32_t bh4[4][4];                                              \
            _Pragma("unroll")                                                \
            for (int nb = 0; nb < 4; ++nb)                                   \
                LDSM_X4(bh4[nb], stg + P_B + bAddr[nb] + ks * 32);           \
            _Pragma("unroll")                                                \
            for (int mf = 0; mf < 2; ++mf) {                                 \
                uint32_t ah[4];                                              \
                LDSM_X4(ah, stg + P_A + aAddr[mf] + ks * 32);                \
                _Pragma("unroll")                                            \
                for (int nb = 0; nb < 4; ++nb) {                             \
                    MMA_F16(acc[mf][2*nb],   ah, bh4[nb][0], bh4[nb][1]);    \
                    MMA_F16(acc[mf][2*nb+1], ah, bh4[nb][2], bh4[nb][3]);    \
                }                                                            \
            }                                                                \
        }                                                                    \
    }

// =================================================================
// QKV GEMM (A plain) with fused RMSNorm+RoPE epilogue.
// =================================================================
__global__ __launch_bounds__(256, 2)
void gemm_qkv(const uint16_t* __restrict__ A, const uint16_t* __restrict__ B,
              const float* __restrict__ qw, const float* __restrict__ kw,
              const float* __restrict__ cosT, const float* __restrict__ sinT,
              uint16_t* __restrict__ qh, uint16_t* __restrict__ kh,
              uint16_t* __restrict__ vh) {
    GEMM_PREAMBLE
    GEMM1_MAINLOOP(A, B, bm, bn)

    const int cb = bn + wn * 64;
    const int sect = cb >> 10;          // 0=Q, 1=K, 2=V
    const int hh = (cb >> 6) & 15;

#pragma unroll
    for (int mf = 0; mf < 2; ++mf) {
#pragma unroll
        for (int hf = 0; hf < 2; ++hf) {
            const int row = bm + wm * 32 + mf * 16 + gid + hf * 8;
            const int s = row & (Ss - 1);
            const int b = row >> 11;
            const size_t dst = (((size_t)(b * Hh + hh)) * Ss + s) * HDd;
            float v[8][2];
#pragma unroll
            for (int nf = 0; nf < 8; ++nf) {
                v[nf][0] = acc[mf][nf][hf * 2];
                v[nf][1] = acc[mf][nf][hf * 2 + 1];
            }
            if (sect == 2) {   // V: plain fp16
#pragma unroll
                for (int nf = 0; nf < 8; ++nf) {
                    int d0 = nf * 8 + tig * 2;
                    *(uint32_t*)&vh[dst + d0] = pack_h2(v[nf][0], v[nf][1]);
                }
            } else {           // Q or K: rms + rope, plain fp16
                float ss = 0.f;
#pragma unroll
                for (int nf = 0; nf < 8; ++nf)
                    ss += v[nf][0] * v[nf][0] + v[nf][1] * v[nf][1];
                ss += __shfl_xor_sync(0xffffffffu, ss, 1);
                ss += __shfl_xor_sync(0xffffffffu, ss, 2);
                float r = rsqrtf(ss * (1.0f / 64.0f) + 1e-6f);
                const float* w = sect ? kw : qw;
                uint16_t* outp = sect ? kh : qh;
                if (sect == 0) r *= SC2;   // fold softmax scale into Q
#pragma unroll
                for (int nf = 0; nf < 4; ++nf) {
                    int d0 = nf * 8 + tig * 2;
                    float2 w1 = *(const float2*)&w[d0];
                    float2 w2 = *(const float2*)&w[d0 + 32];
                    float2 cs = *(const float2*)&cosT[s * 32 + d0];
                    float2 sn = *(const float2*)&sinT[s * 32 + d0];
                    float x1a = v[nf][0]     * r * w1.x;
                    float x1b = v[nf][1]     * r * w1.y;
                    float x2a = v[nf + 4][0] * r * w2.x;
                    float x2b = v[nf + 4][1] * r * w2.y;
                    float o1a = x1a * cs.x - x2a * sn.x;
                    float o1b = x1b * cs.y - x2b * sn.y;
                    float o2a = x2a * cs.x + x1a * sn.x;
                    float o2b = x2b * cs.y + x1b * sn.y;
                    *(uint32_t*)&outp[dst + d0]      = pack_h2(o1a, o1b);
                    *(uint32_t*)&outp[dst + d0 + 32] = pack_h2(o2a, o2b);
                }
            }
        }
    }
}

// =================================================================
// Output-projection GEMM (A plain fp16, fp32 C)
// =================================================================
__global__ __launch_bounds__(256, 2)
void gemm_out(const uint16_t* __restrict__ A, const uint16_t* __restrict__ B,
              float* __restrict__ C) {
    GEMM_PREAMBLE
    GEMM1_MAINLOOP(A, B, bm, bn)
#pragma unroll
    for (int mf = 0; mf < 2; ++mf) {
        const int row = bm + wm * 32 + mf * 16 + gid;
#pragma unroll
        for (int nf = 0; nf < 8; ++nf) {
            const int col = bn + wn * 64 + nf * 8 + tig * 2;
            *(float2*)&C[(size_t)row * Dd + col] =
                make_float2(acc[mf][nf][0], acc[mf][nf][1]);
            *(float2*)&C[(size_t)(row + 8) * Dd + col] =
                make_float2(acc[mf][nf][2], acc[mf][nf][3]);
        }
    }
}

// =================================================================
// fp16 flash attention: Q plain (pre-scaled, frags hoisted), K/V plain.
// P via packed ex2.approx.f16x2 (halves MUFU load).
// Br=128, Bc=64, 256 threads, 4-stage KV ring, 2 CTAs/SM.
// =================================================================
#define APITCH 144
#define A_Q  0
#define A_QSZ 18432               // 128*144
#define A_K  0
#define A_V  9216
#define A_STG 18432
#define ATTN_SMEM (A_QSZ + 4 * A_STG)   // 92160
#define ONES_H2 0x3C003C00u

__device__ __forceinline__ void attn_kv_issue(
    uint32_t stg, const uint16_t* __restrict__ kh,
    const uint16_t* __restrict__ vh, size_t seqbase, int j, int tid) {
#pragma unroll
    for (int u = 0; u < 2; ++u) {
        int q = tid + u * 256;          // 0..511
        int r = q >> 3, c = q & 7;
        size_t src = seqbase + (size_t)(j * 64 + r) * 64 + c * 8;
        uint32_t d = r * APITCH + c * 16;
        cp_async16(stg + A_K + d, kh + src);
        cp_async16(stg + A_V + d, vh + src);
    }
}

__global__ __launch_bounds__(256, 2)
void attn_tc(const uint16_t* __restrict__ qh,
             const uint16_t* __restrict__ kh, const uint16_t* __restrict__ vh,
             const float* __restrict__ sinkl,
             uint16_t* __restrict__ aoh) {
    extern __shared__ char smem[];
    const uint32_t sb = smem_u32(smem);
    const int tid = threadIdx.x;
    const int wid = tid >> 5, lane = tid & 31;
    const int gid = lane >> 2, tig = lane & 3;
    const int qb = gridDim.x - 1 - blockIdx.x;   // heavy tiles first
    const int bh = blockIdx.y;
    const int h  = bh & (Hh - 1);
    const int b  = bh >> 4;
    const size_t seqbase = (size_t)bh * Ss * HDd;
    const int q0 = qb * 128;
    const int jmax = 2 * qb + 1;

    // ---- prologue: Q tile (plain) + KV stages 0,1,2 ----
#pragma unroll
    for (int u = 0; u < 2; ++u) {
        int q = tid + u * 256;              // 0..511
        int r = q >> 2, c = q & 3;          // 128 rows x 4 chunks
        size_t src = seqbase + (size_t)(q0 + r) * 64 + c * 16;
        uint32_t d = r * APITCH + c * 32;
        cp_async16(sb + A_Q + d, qh + src);
        cp_async16(sb + A_Q + d + 16, qh + src + 8);
    }
    attn_kv_issue(sb + A_QSZ, kh, vh, seqbase, 0, tid);
    CP_COMMIT();
    if (1 <= jmax) {
        attn_kv_issue(sb + A_QSZ + A_STG, kh, vh, seqbase, 1, tid);
    }
    CP_COMMIT();
    if (2 <= jmax) {
        attn_kv_issue(sb + A_QSZ + 2 * A_STG, kh, vh, seqbase, 2, tid);
    }
    CP_COMMIT();

    const uint32_t qA = sb + A_Q + (wid * 16 + (lane & 15)) * APITCH
                        + (lane >> 4) * 16;
    uint32_t kB[4];
#pragma unroll
    for (int nb = 0; nb < 4; ++nb)
        kB[nb] = A_K + (nb * 16 + ((lane >> 4) << 3) + (lane & 7)) * APITCH
                 + ((lane >> 3) & 1) * 16;
    const uint32_t vBrel = A_V + (lane & 15) * APITCH + (lane >> 4) * 16;

    const float snk2 = sinkl[h] * LOG2E;
    float m0 = snk2, m1 = snk2;
    float o[8][4], ol[4];
#pragma unroll
    for (int i = 0; i < 8; ++i)
#pragma unroll
        for (int c = 0; c < 4; ++c) o[i][c] = 0.f;
#pragma unroll
    for (int c = 0; c < 4; ++c) ol[c] = 0.f;

    const int r0g = q0 + wid * 16 + gid;
    const int r1g = r0g + 8;

    uint32_t qf[4][4];   // hoisted Q fragments (loaded at j==0)

    for (int j = 0; j <= jmax; ++j) {
        if (j + 2 <= jmax)      { CP_WAIT(2); }
        else if (j + 1 <= jmax) { CP_WAIT(1); }
        else                    { CP_WAIT(0); }
        __syncthreads();
        if (j + 3 <= jmax) {
            attn_kv_issue(sb + A_QSZ + ((j + 3) & 3) * A_STG,
                          kh, vh, seqbase, j + 3, tid);
            CP_COMMIT();
        }
        const uint32_t stg = sb + A_QSZ + (j & 3) * A_STG;

        if (j == 0) {   // Q arrived with KV stage 0; load frags once
#pragma unroll
            for (int ks = 0; ks < 4; ++ks)
                LDSM_X4(qf[ks], qA + ks * 32);
        }

        // ---- S = Q K^T (both plain fp16, Q pre-scaled) ----
        float s[8][4];
#pragma unroll
        for (int i = 0; i < 8; ++i)
#pragma unroll
            for (int c = 0; c < 4; ++c) s[i][c] = 0.f;

#pragma unroll
        for (int ks = 0; ks < 4; ++ks) {
#pragma unroll
            for (int nb = 0; nb < 4; ++nb) {
                uint32_t kb4[4];
                LDSM_X4(kb4, stg + kB[nb] + ks * 32);
                MMA_F16(s[2*nb],   qf[ks], kb4[0], kb4[1]);
                MMA_F16(s[2*nb+1], qf[ks], kb4[2], kb4[3]);
            }
        }

        // ---- causal mask (diagonal blocks only) ----
        if (j >= 2 * qb) {
#pragma unroll
            for (int nf = 0; nf < 8; ++nf)
#pragma unroll
                for (int c = 0; c < 4; ++c) {
                    int col = j * 64 + nf * 8 + tig * 2 + (c & 1);
                    int row = (c < 2) ? r0g : r1g;
                    if (col > row) s[nf][c] = -1e30f;
                }
        }

        // ---- online softmax (base-2) ----
        float mx0 = -1e30f, mx1 = -1e30f;
#pragma unroll
        for (int nf = 0; nf < 8; ++nf) {
            mx0 = fmaxf(mx0, fmaxf(s[nf][0], s[nf][1]));
            mx1 = fmaxf(mx1, fmaxf(s[nf][2], s[nf][3]));
        }
        mx0 = fmaxf(mx0, __shfl_xor_sync(0xffffffffu, mx0, 1));
        mx0 = fmaxf(mx0, __shfl_xor_sync(0xffffffffu, mx0, 2));
        mx1 = fmaxf(mx1, __shfl_xor_sync(0xffffffffu, mx1, 1));
        mx1 = fmaxf(mx1, __shfl_xor_sync(0xffffffffu, mx1, 2));
        const float mn0 = fmaxf(m0, mx0), mn1 = fmaxf(m1, mx1);
        const float cr0 = ex2f(m0 - mn0), cr1 = ex2f(m1 - mn1);
        m0 = mn0; m1 = mn1;
#pragma unroll
        for (int nf = 0; nf < 8; ++nf) {
            o[nf][0] *= cr0; o[nf][1] *= cr0;
            o[nf][2] *= cr1; o[nf][3] *= cr1;
        }
        ol[0] *= cr0; ol[1] *= cr0; ol[2] *= cr1; ol[3] *= cr1;

        // ---- O += P V ;  l += P * ones ----
        // P = 2^(s-m) computed as packed fp16x2 EX2 (half the MUFU ops).
#pragma unroll
        for (int ks = 0; ks < 4; ++ks) {
            uint32_t pa[4];
            pa[0] = ex2_h2(pack_h2(s[2*ks][0]   - mn0, s[2*ks][1]   - mn0));
            pa[1] = ex2_h2(pack_h2(s[2*ks][2]   - mn1, s[2*ks][3]   - mn1));
            pa[2] = ex2_h2(pack_h2(s[2*ks+1][0] - mn0, s[2*ks+1][1] - mn0));
            pa[3] = ex2_h2(pack_h2(s[2*ks+1][2] - mn1, s[2*ks+1][3] - mn1));
            MMA_F16(ol, pa, ONES_H2, ONES_H2);
#pragma unroll
            for (int db = 0; db < 4; ++db) {
                uint32_t vb4[4];
                LDSM_X4_T(vb4, stg + vBrel + ks * 16 * APITCH + db * 32);
                MMA_F16(o[2*db],   pa, vb4[0], vb4[1]);
                MMA_F16(o[2*db+1], pa, vb4[2], vb4[3]);
            }
        }
    }

    // ---- epilogue: add sink to l, normalize, plain fp16 store ----
    const float l0 = ol[0] + ex2f(snk2 - m0);
    const float l1 = ol[2] + ex2f(snk2 - m1);
    const float i0 = 1.f / l0, i1 = 1.f / l1;
#pragma unroll
    for (int nf = 0; nf < 8; ++nf) {
        const int col = h * HDd + nf * 8 + tig * 2;
        {
            size_t idx = ((size_t)(b * Ss + r0g)) * Dd + col;
            *(uint32_t*)&aoh[idx] = pack_h2(o[nf][0] * i0, o[nf][1] * i0);
        }
        {
            size_t idx = ((size_t)(b * Ss + r1g)) * Dd + col;
            *(uint32_t*)&aoh[idx] = pack_h2(o[nf][2] * i1, o[nf][3] * i1);
        }
    }
}

// =================================================================
extern "C" void kernel_launch(void* const* d_in, const int* in_sizes, int n_in,
                              void* d_out, int out_size) {
    const float* x  = (const float*)d_in[0];
    const float* wq = (const float*)d_in[1];
    const float* wk = (const float*)d_in[2];
    const float* wv = (const float*)d_in[3];
    const float* wo = (const float*)d_in[4];
    const float* qw = (const float*)d_in[5];
    const float* kw = (const float*)d_in[6];
    const float* sk = (const float*)d_in[7];
    float* out = (float*)d_out;

    uint16_t *xh, *wh, *woh;
    uint16_t *qhp, *khp, *vhp, *aoh;
    float *cosT, *sinT;
    cudaGetSymbolAddress((void**)&xh,  g_xh);
    cudaGetSymbolAddress((void**)&wh,  g_wh);
    cudaGetSymbolAddress((void**)&woh, g_woh);
    cudaGetSymbolAddress((void**)&qhp, g_qh);
    cudaGetSymbolAddress((void**)&khp, g_kh);
    cudaGetSymbolAddress((void**)&vhp, g_vh);
    cudaGetSymbolAddress((void**)&aoh, g_aoh);
    cudaGetSymbolAddress((void**)&cosT, g_cosT);
    cudaGetSymbolAddress((void**)&sinT, g_sinT);

    cudaFuncSetAttribute(gemm_qkv, cudaFuncAttributeMaxDynamicSharedMemorySize,
                         GEMM1_SMEM);
    cudaFuncSetAttribute(gemm_out, cudaFuncAttributeMaxDynamicSharedMemorySize,
                         GEMM1_SMEM);
    cudaFuncSetAttribute(attn_tc, cudaFuncAttributeMaxDynamicSharedMemorySize,
                         ATTN_SMEM);

    // converts (8192 blocks) + rope tables (256 blocks)
    cvt_all<<<8448, 256>>>((const float4*)x, (const float4*)wq,
                           (const float4*)wk, (const float4*)wv,
                           (const float4*)wo,
                           (uint2*)xh, (uint2*)wh, (uint2*)woh, cosT, sinT);

    // QKV projection + fused norm/rope (128x128 tile, 2 CTAs/SM)
    gemm_qkv<<<dim3(3072 / 128, Mrows / 128), 256, GEMM1_SMEM>>>(
        xh, wh, qw, kw, cosT, sinT, qhp, khp, vhp);

    // flash attention (Q frags hoisted, f16x2 EX2 softmax)
    attn_tc<<<dim3(Ss / 128, Bb * Hh), 256, ATTN_SMEM>>>(
        qhp, khp, vhp, sk, aoh);

    // output projection (128x128 tile, 2 CTAs/SM)
    gemm_out<<<dim3(Dd / 128, Mrows / 128), 256, GEMM1_SMEM>>>(
        aoh, woh, out);
}

// round 17
// speedup vs baseline: 1.6872x; 1.0288x over previous
#include <cuda_runtime.h>
#include <cuda_fp16.h>
#include <stdint.h>
#include <math.h>

// Problem constants
#define Bb   2
#define Ss   2048
#define Dd   1024
#define Hh   16
#define HDd  64
#define Mrows (Bb*Ss)   // 4096

#define SC2 0.18033688011112042f   // 0.125 * log2(e), folded into Q
#define LOG2E 1.4426950408889634f

// ---------------- scratch (no allocs allowed) ----------------
__device__ uint16_t g_xh [Mrows * Dd];            // x fp16 (plain)
__device__ uint16_t g_wh [3072 * Dd];             // fused wq|wk|wv fp16
__device__ uint16_t g_woh[Dd * Dd];               // wo fp16
__device__ uint16_t g_qh [Mrows * Dd];            // [B,H,S,64] fp16 (pre-scaled)
__device__ uint16_t g_kh [Mrows * Dd];            // fp16
__device__ uint16_t g_vh [Mrows * Dd];            // fp16 (plain)
__device__ uint16_t g_aoh[Mrows * Dd];            // attn out fp16 (plain)
__device__ float    g_cosT[Ss * 32];              // rope tables
__device__ float    g_sinT[Ss * 32];

// ================= PTX helpers ==========================
__device__ __forceinline__ uint32_t smem_u32(const void* p) {
    uint32_t a;
    asm("{ .reg .u64 t; cvta.to.shared.u64 t, %1; cvt.u32.u64 %0, t; }"
        : "=r"(a) : "l"(p));
    return a;
}
__device__ __forceinline__ void cp_async16(uint32_t s, const void* g) {
    asm volatile("cp.async.cg.shared.global [%0], [%1], 16;" :: "r"(s), "l"(g));
}
#define CP_COMMIT() asm volatile("cp.async.commit_group;" ::: "memory")
#define CP_WAIT(n)  asm volatile("cp.async.wait_group %0;" :: "n"(n) : "memory")

#define LDSM_X4(r, addr) \
    asm volatile("ldmatrix.sync.aligned.m8n8.x4.shared.b16 {%0,%1,%2,%3}, [%4];" \
        : "=r"((r)[0]), "=r"((r)[1]), "=r"((r)[2]), "=r"((r)[3]) : "r"(addr))
#define LDSM_X4_T(r, addr) \
    asm volatile("ldmatrix.sync.aligned.m8n8.x4.trans.shared.b16 {%0,%1,%2,%3}, [%4];" \
        : "=r"((r)[0]), "=r"((r)[1]), "=r"((r)[2]), "=r"((r)[3]) : "r"(addr))

#define MMA_F16(d, a, b0, b1) \
    asm volatile("mma.sync.aligned.m16n8k16.row.col.f32.f16.f16.f32 " \
        "{%0,%1,%2,%3}, {%4,%5,%6,%7}, {%8,%9}, {%0,%1,%2,%3};" \
        : "+f"((d)[0]), "+f"((d)[1]), "+f"((d)[2]), "+f"((d)[3]) \
        : "r"((a)[0]), "r"((a)[1]), "r"((a)[2]), "r"((a)[3]), \
          "r"(b0), "r"(b1))

__device__ __forceinline__ uint32_t pack_h2(float a, float b) {
    uint32_t r;
    asm("cvt.rn.f16x2.f32 %0, %1, %2;" : "=r"(r) : "f"(b), "f"(a));
    return r;
}
__device__ __forceinline__ float ex2f(float x) {
    float y;
    asm("ex2.approx.f32 %0, %1;" : "=f"(y) : "f"(x));
    return y;
}
// packed fp16x2 exp2
__device__ __forceinline__ uint32_t ex2_h2(uint32_t x) {
    uint32_t y;
    asm("ex2.approx.f16x2 %0, %1;" : "=r"(y) : "r"(x));
    return y;
}

// =================================================================
// fused convert (2 elems/thread): x, w, wo -> fp16 ; rope tables
// =================================================================
__device__ __forceinline__ void cvt_one(
    int i, const float4* __restrict__ x, const float4* __restrict__ wq,
    const float4* __restrict__ wk, const float4* __restrict__ wv,
    const float4* __restrict__ wo,
    uint2* __restrict__ xh, uint2* __restrict__ wh, uint2* __restrict__ woh,
    float* __restrict__ cosT, float* __restrict__ sinT) {
    if (i >= 2097152) {   // rope-table range
        int t = i - 2097152;
        if (t < 65536) {
            int s = t >> 5, j = t & 31;
            float inv = exp2f(-(float)j * 0.4152410118609203f); // log2(1e4)/32
            float sn, cs;
            sincosf((float)s * inv, &sn, &cs);
            cosT[t] = cs;
            sinT[t] = sn;
        }
        return;
    }
    const float4* src;
    uint2* dst;
    if (i < 1048576) {
        src = x + i; dst = xh + i;
    } else {
        int i2 = i - 1048576;
        int reg = i2 >> 18;            // 0..3
        int off = i2 & 262143;
        if (reg == 0)      { src = wq + off; dst = wh + off; }
        else if (reg == 1) { src = wk + off; dst = wh + 262144 + off; }
        else if (reg == 2) { src = wv + off; dst = wh + 524288 + off; }
        else               { src = wo + off; dst = woh + off; }
    }
    float4 v = *src;
    uint2 o;
    o.x = pack_h2(v.x, v.y);
    o.y = pack_h2(v.z, v.w);
    *dst = o;
}

__global__ __launch_bounds__(256)
void cvt_all(const float4* __restrict__ x,  const float4* __restrict__ wq,
             const float4* __restrict__ wk, const float4* __restrict__ wv,
             const float4* __restrict__ wo,
             uint2* __restrict__ xh, uint2* __restrict__ wh,
             uint2* __restrict__ woh,
             float* __restrict__ cosT, float* __restrict__ sinT) {
    int i = (blockIdx.x * 256 + threadIdx.x) * 2;
    cvt_one(i,     x, wq, wk, wv, wo, xh, wh, woh, cosT, sinT);
    cvt_one(i + 1, x, wq, wk, wv, wo, xh, wh, woh, cosT, sinT);
}

// =================================================================
// GEMM framework (proven): plain fp16 HMMA, tile 128x128x64,
// 256 thr, warps 4(M)x2(N), warp 32x64, 3-stage ring, 2 CTAs/SM.
// =================================================================
#define GK 1024
#define GPITCH 144                // 64 f16 = 128B + 16B pad
#define P_A  0                    // 128*144 = 18432
#define P_B  18432
#define P_STG 36864
#define GEMM1_SMEM (3 * P_STG)    // 110592

#define GEMM_PREAMBLE                                                        \
    extern __shared__ char smem[];                                           \
    const uint32_t sb = smem_u32(smem);                                      \
    const int tid = threadIdx.x;                                             \
    const int wid = tid >> 5, lane = tid & 31;                               \
    const int wm = wid & 3, wn = wid >> 2;                                   \
    const int gid = lane >> 2, tig = lane & 3;                               \
    const int bm = blockIdx.y * 128, bn = blockIdx.x * 128;                  \
    uint32_t aAddr[2], bAddr[4];                                             \
    _Pragma("unroll")                                                        \
    for (int mf = 0; mf < 2; ++mf)                                           \
        aAddr[mf] = (wm * 32 + mf * 16 + (lane & 15)) * GPITCH               \
                    + (lane >> 4) * 16;                                      \
    _Pragma("unroll")                                                        \
    for (int nb = 0; nb < 4; ++nb)                                           \
        bAddr[nb] = (wn * 64 + nb * 16 + ((lane >> 4) << 3)                  \
                    + (lane & 7)) * GPITCH + ((lane >> 3) & 1) * 16;         \
    float acc[2][8][4];                                                      \
    _Pragma("unroll")                                                        \
    for (int i = 0; i < 2; ++i)                                              \
        _Pragma("unroll")                                                    \
        for (int j = 0; j < 8; ++j)                                          \
            _Pragma("unroll")                                                \
            for (int c = 0; c < 4; ++c) acc[i][j][c] = 0.f;

__device__ __forceinline__ void gemm1_issue(
    uint32_t stg, const uint16_t* __restrict__ A,
    const uint16_t* __restrict__ B, int bm, int bn, int k0, int tid) {
#pragma unroll
    for (int u = 0; u < 4; ++u) {
        int q = tid + u * 256;          // 0..1023
        int r = q >> 3, c = q & 7;
        uint32_t d = r * GPITCH + c * 16;
        cp_async16(stg + P_A + d, A + (size_t)(bm + r) * GK + k0 + c * 8);
        cp_async16(stg + P_B + d, B + (size_t)(bn + r) * GK + k0 + c * 8);
    }
}

#define GEMM1_MAINLOOP(A, B, bm, bn)                                         \
    gemm1_issue(sb, A, B, bm, bn, 0, tid);                                   \
    CP_COMMIT();                                                             \
    gemm1_issue(sb + P_STG, A, B, bm, bn, 64, tid);                          \
    CP_COMMIT();                                                             \
    for (int s = 0; s < 16; ++s) {                                           \
        if (s < 15) { CP_WAIT(1); } else { CP_WAIT(0); }                     \
        __syncthreads();                                                     \
        if (s + 2 < 16) {                                                    \
            gemm1_issue(sb + ((s + 2) % 3) * P_STG, A, B,                    \
                        bm, bn, (s + 2) * 64, tid);                          \
            CP_COMMIT();                                                     \
        }                                                                    \
        const uint32_t stg = sb + (s % 3) * P_STG;                           \
        _Pragma("unroll")                                                    \
        for (int ks = 0; ks < 4; ++ks) {                                     \
            uint32_t bh4[4][4];                                              \
            _Pragma("unroll")                                                \
            for (int nb = 0; nb < 4; ++nb)                                   \
                LDSM_X4(bh4[nb], stg + P_B + bAddr[nb] + ks * 32);           \
            _Pragma("unroll")                                                \
            for (int mf = 0; mf < 2; ++mf) {                                 \
                uint32_t ah[4];                                              \
                LDSM_X4(ah, stg + P_A + aAddr[mf] + ks * 32);                \
                _Pragma("unroll")                                            \
                for (int nb = 0; nb < 4; ++nb) {                             \
                    MMA_F16(acc[mf][2*nb],   ah, bh4[nb][0], bh4[nb][1]);    \
                    MMA_F16(acc[mf][2*nb+1], ah, bh4[nb][2], bh4[nb][3]);    \
                }                                                            \
            }                                                                \
        }                                                                    \
    }

// =================================================================
// QKV GEMM (A plain) with fused RMSNorm+RoPE epilogue.
// =================================================================
__global__ __launch_bounds__(256, 2)
void gemm_qkv(const uint16_t* __restrict__ A, const uint16_t* __restrict__ B,
              const float* __restrict__ qw, const float* __restrict__ kw,
              const float* __restrict__ cosT, const float* __restrict__ sinT,
              uint16_t* __restrict__ qh, uint16_t* __restrict__ kh,
              uint16_t* __restrict__ vh) {
    GEMM_PREAMBLE
    GEMM1_MAINLOOP(A, B, bm, bn)

    const int cb = bn + wn * 64;
    const int sect = cb >> 10;          // 0=Q, 1=K, 2=V
    const int hh = (cb >> 6) & 15;

#pragma unroll
    for (int mf = 0; mf < 2; ++mf) {
#pragma unroll
        for (int hf = 0; hf < 2; ++hf) {
            const int row = bm + wm * 32 + mf * 16 + gid + hf * 8;
            const int s = row & (Ss - 1);
            const int b = row >> 11;
            const size_t dst = (((size_t)(b * Hh + hh)) * Ss + s) * HDd;
            float v[8][2];
#pragma unroll
            for (int nf = 0; nf < 8; ++nf) {
                v[nf][0] = acc[mf][nf][hf * 2];
                v[nf][1] = acc[mf][nf][hf * 2 + 1];
            }
            if (sect == 2) {   // V: plain fp16
#pragma unroll
                for (int nf = 0; nf < 8; ++nf) {
                    int d0 = nf * 8 + tig * 2;
                    *(uint32_t*)&vh[dst + d0] = pack_h2(v[nf][0], v[nf][1]);
                }
            } else {           // Q or K: rms + rope, plain fp16
                float ss = 0.f;
#pragma unroll
                for (int nf = 0; nf < 8; ++nf)
                    ss += v[nf][0] * v[nf][0] + v[nf][1] * v[nf][1];
                ss += __shfl_xor_sync(0xffffffffu, ss, 1);
                ss += __shfl_xor_sync(0xffffffffu, ss, 2);
                float r = rsqrtf(ss * (1.0f / 64.0f) + 1e-6f);
                const float* w = sect ? kw : qw;
                uint16_t* outp = sect ? kh : qh;
                if (sect == 0) r *= SC2;   // fold softmax scale into Q
#pragma unroll
                for (int nf = 0; nf < 4; ++nf) {
                    int d0 = nf * 8 + tig * 2;
                    float2 w1 = *(const float2*)&w[d0];
                    float2 w2 = *(const float2*)&w[d0 + 32];
                    float2 cs = *(const float2*)&cosT[s * 32 + d0];
                    float2 sn = *(const float2*)&sinT[s * 32 + d0];
                    float x1a = v[nf][0]     * r * w1.x;
                    float x1b = v[nf][1]     * r * w1.y;
                    float x2a = v[nf + 4][0] * r * w2.x;
                    float x2b = v[nf + 4][1] * r * w2.y;
                    float o1a = x1a * cs.x - x2a * sn.x;
                    float o1b = x1b * cs.y - x2b * sn.y;
                    float o2a = x2a * cs.x + x1a * sn.x;
                    float o2b = x2b * cs.y + x1b * sn.y;
                    *(uint32_t*)&outp[dst + d0]      = pack_h2(o1a, o1b);
                    *(uint32_t*)&outp[dst + d0 + 32] = pack_h2(o2a, o2b);
                }
            }
        }
    }
}

// =================================================================
// Output-projection GEMM (A plain fp16, fp32 C)
// =================================================================
__global__ __launch_bounds__(256, 2)
void gemm_out(const uint16_t* __restrict__ A, const uint16_t* __restrict__ B,
              float* __restrict__ C) {
    GEMM_PREAMBLE
    GEMM1_MAINLOOP(A, B, bm, bn)
#pragma unroll
    for (int mf = 0; mf < 2; ++mf) {
        const int row = bm + wm * 32 + mf * 16 + gid;
#pragma unroll
        for (int nf = 0; nf < 8; ++nf) {
            const int col = bn + wn * 64 + nf * 8 + tig * 2;
            *(float2*)&C[(size_t)row * Dd + col] =
                make_float2(acc[mf][nf][0], acc[mf][nf][1]);
            *(float2*)&C[(size_t)(row + 8) * Dd + col] =
                make_float2(acc[mf][nf][2], acc[mf][nf][3]);
        }
    }
}

// =================================================================
// fp16 flash attention, max-free softmax:
//   |logit| <= 8*log2e = 11.54 (RMS-normed q,k, Cauchy-Schwarz), so
//   P = 2^s fits fp16 (max 2^11.54 = 2980 < 65504); no running max,
//   no rescale. l = sum P (ones-MMA) + 2^sink; out = PV / l.
// Br=128, Bc=64, 256 threads, 4-stage KV ring, 2 CTAs/SM.
// =================================================================
#define APITCH 144
#define A_Q  0
#define A_QSZ 18432               // 128*144
#define A_K  0
#define A_V  9216
#define A_STG 18432
#define ATTN_SMEM (A_QSZ + 4 * A_STG)   // 92160
#define ONES_H2 0x3C003C00u

__device__ __forceinline__ void attn_kv_issue(
    uint32_t stg, const uint16_t* __restrict__ kh,
    const uint16_t* __restrict__ vh, size_t seqbase, int j, int tid) {
#pragma unroll
    for (int u = 0; u < 2; ++u) {
        int q = tid + u * 256;          // 0..511
        int r = q >> 3, c = q & 7;
        size_t src = seqbase + (size_t)(j * 64 + r) * 64 + c * 8;
        uint32_t d = r * APITCH + c * 16;
        cp_async16(stg + A_K + d, kh + src);
        cp_async16(stg + A_V + d, vh + src);
    }
}

__global__ __launch_bounds__(256, 2)
void attn_tc(const uint16_t* __restrict__ qh,
             const uint16_t* __restrict__ kh, const uint16_t* __restrict__ vh,
             const float* __restrict__ sinkl,
             uint16_t* __restrict__ aoh) {
    extern __shared__ char smem[];
    const uint32_t sb = smem_u32(smem);
    const int tid = threadIdx.x;
    const int wid = tid >> 5, lane = tid & 31;
    const int gid = lane >> 2, tig = lane & 3;
    const int qb = gridDim.x - 1 - blockIdx.x;   // heavy tiles first
    const int bh = blockIdx.y;
    const int h  = bh & (Hh - 1);
    const int b  = bh >> 4;
    const size_t seqbase = (size_t)bh * Ss * HDd;
    const int q0 = qb * 128;
    const int jmax = 2 * qb + 1;

    // ---- prologue: Q tile (plain) + KV stages 0,1,2 ----
#pragma unroll
    for (int u = 0; u < 2; ++u) {
        int q = tid + u * 256;              // 0..511
        int r = q >> 2, c = q & 3;          // 128 rows x 4 chunks
        size_t src = seqbase + (size_t)(q0 + r) * 64 + c * 16;
        uint32_t d = r * APITCH + c * 32;
        cp_async16(sb + A_Q + d, qh + src);
        cp_async16(sb + A_Q + d + 16, qh + src + 8);
    }
    attn_kv_issue(sb + A_QSZ, kh, vh, seqbase, 0, tid);
    CP_COMMIT();
    if (1 <= jmax) {
        attn_kv_issue(sb + A_QSZ + A_STG, kh, vh, seqbase, 1, tid);
    }
    CP_COMMIT();
    if (2 <= jmax) {
        attn_kv_issue(sb + A_QSZ + 2 * A_STG, kh, vh, seqbase, 2, tid);
    }
    CP_COMMIT();

    const uint32_t qA = sb + A_Q + (wid * 16 + (lane & 15)) * APITCH
                        + (lane >> 4) * 16;
    uint32_t kB[4];
#pragma unroll
    for (int nb = 0; nb < 4; ++nb)
        kB[nb] = A_K + (nb * 16 + ((lane >> 4) << 3) + (lane & 7)) * APITCH
                 + ((lane >> 3) & 1) * 16;
    const uint32_t vBrel = A_V + (lane & 15) * APITCH + (lane >> 4) * 16;

    float o[8][4], ol[4];
#pragma unroll
    for (int i = 0; i < 8; ++i)
#pragma unroll
        for (int c = 0; c < 4; ++c) o[i][c] = 0.f;
#pragma unroll
    for (int c = 0; c < 4; ++c) ol[c] = 0.f;

    const int r0g = q0 + wid * 16 + gid;
    const int r1g = r0g + 8;

    uint32_t qf[4][4];   // hoisted Q fragments (loaded at j==0)

    for (int j = 0; j <= jmax; ++j) {
        if (j + 2 <= jmax)      { CP_WAIT(2); }
        else if (j + 1 <= jmax) { CP_WAIT(1); }
        else                    { CP_WAIT(0); }
        __syncthreads();
        if (j + 3 <= jmax) {
            attn_kv_issue(sb + A_QSZ + ((j + 3) & 3) * A_STG,
                          kh, vh, seqbase, j + 3, tid);
            CP_COMMIT();
        }
        const uint32_t stg = sb + A_QSZ + (j & 3) * A_STG;

        if (j == 0) {   // Q arrived with KV stage 0; load frags once
#pragma unroll
            for (int ks = 0; ks < 4; ++ks)
                LDSM_X4(qf[ks], qA + ks * 32);
        }

        // ---- S = Q K^T (both plain fp16, Q pre-scaled to log2-dom.) ----
        float s[8][4];
#pragma unroll
        for (int i = 0; i < 8; ++i)
#pragma unroll
            for (int c = 0; c < 4; ++c) s[i][c] = 0.f;

#pragma unroll
        for (int ks = 0; ks < 4; ++ks) {
#pragma unroll
            for (int nb = 0; nb < 4; ++nb) {
                uint32_t kb4[4];
                LDSM_X4(kb4, stg + kB[nb] + ks * 32);
                MMA_F16(s[2*nb],   qf[ks], kb4[0], kb4[1]);
                MMA_F16(s[2*nb+1], qf[ks], kb4[2], kb4[3]);
            }
        }

        // ---- causal mask (diagonal blocks only) ----
        if (j >= 2 * qb) {
#pragma unroll
            for (int nf = 0; nf < 8; ++nf)
#pragma unroll
                for (int c = 0; c < 4; ++c) {
                    int col = j * 64 + nf * 8 + tig * 2 + (c & 1);
                    int row = (c < 2) ? r0g : r1g;
                    if (col > row) s[nf][c] = -1e30f;   // fp16 -inf -> P=0
                }
        }

        // ---- P = 2^s (packed fp16x2 EX2; no max, no rescale) ----
        // O += P V ;  l += P * ones
#pragma unroll
        for (int ks = 0; ks < 4; ++ks) {
            uint32_t pa[4];
            pa[0] = ex2_h2(pack_h2(s[2*ks][0],   s[2*ks][1]));
            pa[1] = ex2_h2(pack_h2(s[2*ks][2],   s[2*ks][3]));
            pa[2] = ex2_h2(pack_h2(s[2*ks+1][0], s[2*ks+1][1]));
            pa[3] = ex2_h2(pack_h2(s[2*ks+1][2], s[2*ks+1][3]));
            MMA_F16(ol, pa, ONES_H2, ONES_H2);
#pragma unroll
            for (int db = 0; db < 4; ++db) {
                uint32_t vb4[4];
                LDSM_X4_T(vb4, stg + vBrel + ks * 16 * APITCH + db * 32);
                MMA_F16(o[2*db],   pa, vb4[0], vb4[1]);
                MMA_F16(o[2*db+1], pa, vb4[2], vb4[3]);
            }
        }
    }

    // ---- epilogue: add sink to l, normalize, plain fp16 store ----
    const float snk2 = sinkl[h] * LOG2E;
    const float sv = ex2f(snk2);
    const float i0 = 1.f / (ol[0] + sv);
    const float i1 = 1.f / (ol[2] + sv);
#pragma unroll
    for (int nf = 0; nf < 8; ++nf) {
        const int col = h * HDd + nf * 8 + tig * 2;
        {
            size_t idx = ((size_t)(b * Ss + r0g)) * Dd + col;
            *(uint32_t*)&aoh[idx] = pack_h2(o[nf][0] * i0, o[nf][1] * i0);
        }
        {
            size_t idx = ((size_t)(b * Ss + r1g)) * Dd + col;
            *(uint32_t*)&aoh[idx] = pack_h2(o[nf][2] * i1, o[nf][3] * i1);
        }
    }
}

// =================================================================
extern "C" void kernel_launch(void* const* d_in, const int* in_sizes, int n_in,
                              void* d_out, int out_size) {
    const float* x  = (const float*)d_in[0];
    const float* wq = (const float*)d_in[1];
    const float* wk = (const float*)d_in[2];
    const float* wv = (const float*)d_in[3];
    const float* wo = (const float*)d_in[4];
    const float* qw = (const float*)d_in[5];
    const float* kw = (const float*)d_in[6];
    const float* sk = (const float*)d_in[7];
    float* out = (float*)d_out;

    uint16_t *xh, *wh, *woh;
    uint16_t *qhp, *khp, *vhp, *aoh;
    float *cosT, *sinT;
    cudaGetSymbolAddress((void**)&xh,  g_xh);
    cudaGetSymbolAddress((void**)&wh,  g_wh);
    cudaGetSymbolAddress((void**)&woh, g_woh);
    cudaGetSymbolAddress((void**)&qhp, g_qh);
    cudaGetSymbolAddress((void**)&khp, g_kh);
    cudaGetSymbolAddress((void**)&vhp, g_vh);
    cudaGetSymbolAddress((void**)&aoh, g_aoh);
    cudaGetSymbolAddress((void**)&cosT, g_cosT);
    cudaGetSymbolAddress((void**)&sinT, g_sinT);

    cudaFuncSetAttribute(gemm_qkv, cudaFuncAttributeMaxDynamicSharedMemorySize,
                         GEMM1_SMEM);
    cudaFuncSetAttribute(gemm_out, cudaFuncAttributeMaxDynamicSharedMemorySize,
                         GEMM1_SMEM);
    cudaFuncSetAttribute(attn_tc, cudaFuncAttributeMaxDynamicSharedMemorySize,
                         ATTN_SMEM);

    // converts + rope tables (2 elements/thread)
    cvt_all<<<4224, 256>>>((const float4*)x, (const float4*)wq,
                           (const float4*)wk, (const float4*)wv,
                           (const float4*)wo,
                           (uint2*)xh, (uint2*)wh, (uint2*)woh, cosT, sinT);

    // QKV projection + fused norm/rope (128x128 tile, 2 CTAs/SM)
    gemm_qkv<<<dim3(3072 / 128, Mrows / 128), 256, GEMM1_SMEM>>>(
        xh, wh, qw, kw, cosT, sinT, qhp, khp, vhp);

    // flash attention (max-free softmax)
    attn_tc<<<dim3(Ss / 128, Bb * Hh), 256, ATTN_SMEM>>>(
        qhp, khp, vhp, sk, aoh);

    // output projection (128x128 tile, 2 CTAs/SM)
    gemm_out<<<dim3(Dd / 128, Mrows / 128), 256, GEMM1_SMEM>>>(
        aoh, woh, out);
}